// round 13
// baseline (speedup 1.0000x reference)
#include <cuda_runtime.h>
#include <cuda_bf16.h>
#include <cuda_fp16.h>
#include <math.h>
#include <stdint.h>

#define SEQ      2048
#define DIM      1280
#define HEADS    16
#define HEAD_DIM 80
#define QKV_DIM  3840

// ---------------------------------------------------------------------------
// Scratch
// ---------------------------------------------------------------------------
__device__ float g_qkv[SEQ * QKV_DIM];
__device__ __half g_hid_h[SEQ * DIM];
__device__ __half g_wq_h[QKV_DIM * DIM], g_wq_l[QKV_DIM * DIM];
__device__ __half g_wp_h[DIM * DIM],     g_wp_l[DIM * DIM];
__device__ __half g_at_h[SEQ * DIM];
__device__ __nv_bfloat16 g_q_h[HEADS * SEQ * HEAD_DIM], g_q_l[HEADS * SEQ * HEAD_DIM];
__device__ __nv_bfloat16 g_k_h[HEADS * SEQ * HEAD_DIM], g_k_l[HEADS * SEQ * HEAD_DIM];
__device__ __nv_bfloat16 g_vt_h[HEADS * HEAD_DIM * SEQ], g_vt_l[HEADS * HEAD_DIM * SEQ];

// ---------------------------------------------------------------------------
// PTX helpers
// ---------------------------------------------------------------------------
#define CP_ASYNC16(dst, src) \
    asm volatile("cp.async.cg.shared.global [%0], [%1], 16;" :: "r"(dst), "l"(src))
#define CP_COMMIT() asm volatile("cp.async.commit_group;")
#define CP_WAIT(n)  asm volatile("cp.async.wait_group %0;" :: "n"(n))

#define LDSM_X4(r0,r1,r2,r3,addr) \
    asm volatile("ldmatrix.sync.aligned.m8n8.x4.shared.b16 {%0,%1,%2,%3}, [%4];" \
        : "=r"(r0),"=r"(r1),"=r"(r2),"=r"(r3) : "r"(addr))
#define LDSM_X2(r0,r1,addr) \
    asm volatile("ldmatrix.sync.aligned.m8n8.x2.shared.b16 {%0,%1}, [%2];" \
        : "=r"(r0),"=r"(r1) : "r"(addr))

#define MMA16816(c0,c1,c2,c3,a0,a1,a2,a3,b0,b1) \
    asm volatile("mma.sync.aligned.m16n8k16.row.col.f32.bf16.bf16.f32 " \
        "{%0,%1,%2,%3}, {%4,%5,%6,%7}, {%8,%9}, {%0,%1,%2,%3};" \
        : "+f"(c0),"+f"(c1),"+f"(c2),"+f"(c3) \
        : "r"(a0),"r"(a1),"r"(a2),"r"(a3),"r"(b0),"r"(b1))

#define MMAH16816(c0,c1,c2,c3,a0,a1,a2,a3,b0,b1) \
    asm volatile("mma.sync.aligned.m16n8k16.row.col.f32.f16.f16.f32 " \
        "{%0,%1,%2,%3}, {%4,%5,%6,%7}, {%8,%9}, {%0,%1,%2,%3};" \
        : "+f"(c0),"+f"(c1),"+f"(c2),"+f"(c3) \
        : "r"(a0),"r"(a1),"r"(a2),"r"(a3),"r"(b0),"r"(b1))

__device__ __forceinline__ uint32_t smem_u32(const void* p) {
    return (uint32_t)__cvta_generic_to_shared(p);
}
__device__ __forceinline__ uint32_t pack_bf2(float a, float b) {
    __nv_bfloat162 v = __float22bfloat162_rn(make_float2(a, b));
    return *(uint32_t*)&v;
}
__device__ __forceinline__ uint32_t pack_h2(float a, float b) {
    __half2 v = __floats2half2_rn(a, b);
    return *(uint32_t*)&v;
}

// ---------------------------------------------------------------------------
// fp16 2-term HGEMM (round-10, at HMMA roofline — unchanged)
// ---------------------------------------------------------------------------
#define KBLK 32
#define KPAD 40
#define APLANE_B (128 * KPAD * 2)
#define BPLANE_B (64 * KPAD * 2)
#define STAGE_B (APLANE_B + 2 * BPLANE_B)
#define HG_SMEM (2 * STAGE_B)

__global__ void __launch_bounds__(256, 3) hgemm2_kernel(
    const __half* __restrict__ Ah_,
    const __half* __restrict__ Bh_, const __half* __restrict__ Bl_,
    const float* __restrict__ bias, float* __restrict__ C,
    int M, int N, int K)
{
    extern __shared__ char smraw[];
    const uint32_t sb = smem_u32(smraw);

    const int tid = threadIdx.x;
    const int ln  = tid & 31;
    const int wid = tid >> 5;
    const int wm  = wid >> 1;
    const int wn  = wid & 1;
    const int m0  = blockIdx.y * 128;
    const int n0  = blockIdx.x * 64;

    const __half* gA = Ah_ + (size_t)m0 * K;
    const __half* gB[2] = { Bh_ + (size_t)n0 * K, Bl_ + (size_t)n0 * K };

    const int arow0 = tid >> 2;
    const int arow1 = (tid + 256) >> 2;
    const int brow  = tid >> 2;
    const int kc16  = (tid & 3) * 8;

    auto load_stage = [&](int kt, int s) {
        const uint32_t stb = sb + s * STAGE_B;
        CP_ASYNC16(stb + (uint32_t)(arow0 * KPAD + kc16) * 2,
                   gA + (size_t)arow0 * K + kt + kc16);
        CP_ASYNC16(stb + (uint32_t)(arow1 * KPAD + kc16) * 2,
                   gA + (size_t)arow1 * K + kt + kc16);
        #pragma unroll
        for (int p = 0; p < 2; p++) {
            const uint32_t pb = stb + APLANE_B + p * BPLANE_B;
            CP_ASYNC16(pb + (uint32_t)(brow * KPAD + kc16) * 2,
                       gB[p] + (size_t)brow * K + kt + kc16);
        }
        CP_COMMIT();
    };

    float acc[2][4][4];
    #pragma unroll
    for (int mi = 0; mi < 2; mi++)
        #pragma unroll
        for (int ni = 0; ni < 4; ni++)
            #pragma unroll
            for (int c = 0; c < 4; c++) acc[mi][ni][c] = 0.f;

    load_stage(0, 0);
    CP_WAIT(0);
    __syncthreads();

    const int a_row = (ln & 15);
    const int a_kof = (ln < 16) ? 0 : 8;
    const int b_row = (ln & 7);
    const int b_kof = (ln & 8);

    int buf = 0;
    for (int kt = 0; kt < K; kt += KBLK) {
        const bool hasNext = (kt + KBLK) < K;
        if (hasNext) load_stage(kt + KBLK, buf ^ 1);

        const uint32_t stb = sb + buf * STAGE_B;
        const uint32_t pAh = stb;
        const uint32_t pBh = stb + APLANE_B;
        const uint32_t pBl = stb + APLANE_B + BPLANE_B;

        #pragma unroll
        for (int ks = 0; ks < 2; ks++) {
            const int k0 = ks * 16;
            uint32_t ah[2][4];
            #pragma unroll
            for (int mi = 0; mi < 2; mi++) {
                uint32_t off = (uint32_t)((wm * 32 + mi * 16 + a_row) * KPAD
                                          + k0 + a_kof) * 2;
                LDSM_X4(ah[mi][0], ah[mi][1], ah[mi][2], ah[mi][3], pAh + off);
            }
            uint32_t bh[4][2], bl[4][2];
            #pragma unroll
            for (int ni = 0; ni < 4; ni++) {
                uint32_t off = (uint32_t)((wn * 32 + ni * 8 + b_row) * KPAD
                                          + k0 + b_kof) * 2;
                LDSM_X2(bh[ni][0], bh[ni][1], pBh + off);
                LDSM_X2(bl[ni][0], bl[ni][1], pBl + off);
            }
            #pragma unroll
            for (int ni = 0; ni < 4; ni++)
                #pragma unroll
                for (int mi = 0; mi < 2; mi++)
                    MMAH16816(acc[mi][ni][0], acc[mi][ni][1],
                              acc[mi][ni][2], acc[mi][ni][3],
                              ah[mi][0], ah[mi][1], ah[mi][2], ah[mi][3],
                              bh[ni][0], bh[ni][1]);
            #pragma unroll
            for (int ni = 0; ni < 4; ni++)
                #pragma unroll
                for (int mi = 0; mi < 2; mi++)
                    MMAH16816(acc[mi][ni][0], acc[mi][ni][1],
                              acc[mi][ni][2], acc[mi][ni][3],
                              ah[mi][0], ah[mi][1], ah[mi][2], ah[mi][3],
                              bl[ni][0], bl[ni][1]);
        }

        if (hasNext) {
            CP_WAIT(0);
            __syncthreads();
            buf ^= 1;
        }
    }

    const int crow = ln >> 2;
    const int ccol = (ln & 3) * 2;
    #pragma unroll
    for (int mi = 0; mi < 2; mi++) {
        #pragma unroll
        for (int ni = 0; ni < 4; ni++) {
            int col = n0 + wn * 32 + ni * 8 + ccol;
            float b0 = bias[col], b1 = bias[col + 1];
            int r0 = m0 + wm * 32 + mi * 16 + crow;
            float2 v0 = make_float2(acc[mi][ni][0] + b0, acc[mi][ni][1] + b1);
            float2 v1 = make_float2(acc[mi][ni][2] + b0, acc[mi][ni][3] + b1);
            *(float2*)(C + (size_t)r0 * N + col)       = v0;
            *(float2*)(C + (size_t)(r0 + 8) * N + col) = v1;
        }
    }
}

// ---------------------------------------------------------------------------
// Merged decompose: hidden (hi only) + qkv_w (hi/lo) + proj_w (hi/lo)
// ---------------------------------------------------------------------------
#define HID4 (SEQ * DIM / 4)
#define WQ4  (QKV_DIM * DIM / 4)
#define WP4  (DIM * DIM / 4)

__global__ void __launch_bounds__(256) decomp_all_kernel(
    const float4* __restrict__ hid, const float4* __restrict__ wq,
    const float4* __restrict__ wp,
    uint32_t* __restrict__ hidH,
    uint32_t* __restrict__ wqH, uint32_t* __restrict__ wqL,
    uint32_t* __restrict__ wpH, uint32_t* __restrict__ wpL)
{
    int idx = blockIdx.x * blockDim.x + threadIdx.x;
    if (idx < HID4) {
        float4 v = hid[idx];
        hidH[idx * 2]     = pack_h2(v.x, v.y);
        hidH[idx * 2 + 1] = pack_h2(v.z, v.w);
        return;
    }
    const float4* src;
    uint32_t *dh, *dl;
    int j;
    if (idx < HID4 + WQ4) {
        j = idx - HID4;  src = wq; dh = wqH; dl = wqL;
    } else if (idx < HID4 + WQ4 + WP4) {
        j = idx - HID4 - WQ4;  src = wp; dh = wpH; dl = wpL;
    } else return;

    float4 v = src[j];
    __half h0 = __float2half_rn(v.x);
    __half h1 = __float2half_rn(v.y);
    __half h2 = __float2half_rn(v.z);
    __half h3 = __float2half_rn(v.w);
    dh[j * 2]     = pack_h2(v.x, v.y);
    dh[j * 2 + 1] = pack_h2(v.z, v.w);
    dl[j * 2]     = pack_h2(v.x - __half2float(h0), v.y - __half2float(h1));
    dl[j * 2 + 1] = pack_h2(v.z - __half2float(h2), v.w - __half2float(h3));
}

// ---------------------------------------------------------------------------
// Merged prep: blockIdx.y < HEADS  -> V transpose+decomp for (s0, head)
//              blockIdx.y == HEADS -> rope+scale+decomp for s in [s0, s0+64)
// ---------------------------------------------------------------------------
__global__ void __launch_bounds__(256) prep_kernel(const float* __restrict__ rot)
{
    const int tid = threadIdx.x;
    const int s0  = blockIdx.x * 64;

    if (blockIdx.y < HEADS) {
        // ---- V transpose + hi/lo decomp ----
        __shared__ float T[HEAD_DIM][65];
        const int h = blockIdx.y;
        #pragma unroll
        for (int i = 0; i < 20; i++) {
            int idx = tid + i * 256;
            int r = idx / HEAD_DIM, d = idx % HEAD_DIM;
            T[d][r] = g_qkv[(size_t)(s0 + r) * QKV_DIM + 2 * DIM + h * HEAD_DIM + d];
        }
        __syncthreads();
        #pragma unroll
        for (int i = 0; i < 20; i++) {
            int idx = tid + i * 256;
            int d = idx / 64, r = idx % 64;
            float v = T[d][r];
            __nv_bfloat16 hi = __float2bfloat16(v);
            size_t o = ((size_t)h * HEAD_DIM + d) * SEQ + s0 + r;
            g_vt_h[o] = hi;
            g_vt_l[o] = __float2bfloat16(v - __bfloat162float(hi));
        }
    } else {
        // ---- Q/K rope + scale + hi/lo decomp; sincos reused across heads ----
        const float scale = rsqrtf((float)HEAD_DIM);
        #pragma unroll
        for (int i = 0; i < 10; i++) {
            int idx = tid + i * 256;       // 64 * 40 = 2560 items
            int d2 = idx % 40;
            int s  = s0 + idx / 40;
            float f = rot[s * 40 + d2];
            float si, co;
            sincosf(f, &si, &co);
            #pragma unroll 4
            for (int h = 0; h < HEADS; h++) {
                size_t qb = (size_t)s * QKV_DIM + h * HEAD_DIM;
                float q1 = g_qkv[qb + d2],        q2 = g_qkv[qb + 40 + d2];
                float k1 = g_qkv[qb + DIM + d2],  k2 = g_qkv[qb + DIM + 40 + d2];
                float qr1 = (q1 * co - q2 * si) * scale;
                float qr2 = (q2 * co + q1 * si) * scale;
                float kr1 = k1 * co - k2 * si;
                float kr2 = k2 * co + k1 * si;
                size_t ob = ((size_t)h * SEQ + s) * HEAD_DIM;
                __nv_bfloat16 hq1 = __float2bfloat16(qr1);
                __nv_bfloat16 hq2 = __float2bfloat16(qr2);
                __nv_bfloat16 hk1 = __float2bfloat16(kr1);
                __nv_bfloat16 hk2 = __float2bfloat16(kr2);
                g_q_h[ob + d2]      = hq1;
                g_q_h[ob + 40 + d2] = hq2;
                g_q_l[ob + d2]      = __float2bfloat16(qr1 - __bfloat162float(hq1));
                g_q_l[ob + 40 + d2] = __float2bfloat16(qr2 - __bfloat162float(hq2));
                g_k_h[ob + d2]      = hk1;
                g_k_h[ob + 40 + d2] = hk2;
                g_k_l[ob + d2]      = __float2bfloat16(kr1 - __bfloat162float(hk1));
                g_k_l[ob + 40 + d2] = __float2bfloat16(kr2 - __bfloat162float(hk2));
            }
        }
    }
}

// ---------------------------------------------------------------------------
// Tensor-core flash attention: AK=32, 2 CTAs/SM, unmasked fast path.
// ---------------------------------------------------------------------------
#define AQ    128
#define AK    32
#define QSTR  88
#define VSTR  40
#define QPL   (AQ * QSTR * 2)
#define KPL   (AK * QSTR * 2)
#define VPL   (HEAD_DIM * VSTR * 2)
#define KSTG  (2 * KPL)
#define VSTG  (2 * VPL)
#define FA_SMEM (2*QPL + 2*KSTG + 2*VSTG + (AQ + 2*AK + 8) * 4)

__global__ void __launch_bounds__(256, 2) fattn_kernel(const int* __restrict__ cu, int ncu)
{
    extern __shared__ char smraw[];
    char* Qb  = smraw;
    char* Kb  = Qb + 2 * QPL;
    char* Vb  = Kb + 2 * KSTG;
    int* segq  = (int*)(Vb + 2 * VSTG);
    int* segk  = segq + AQ;
    int* range = segk + 2 * AK;        // [0]=lo [1]=hi [2]=nomask

    const int tid = threadIdx.x;
    const int w   = tid >> 5;
    const int ln  = tid & 31;
    const int head  = blockIdx.y;
    const int qbase = blockIdx.x * AQ;

    const __nv_bfloat16* gq[2] = { g_q_h, g_q_l };
    const __nv_bfloat16* gk[2] = { g_k_h, g_k_l };
    const __nv_bfloat16* gv[2] = { g_vt_h, g_vt_l };

    {
        const uint32_t qs = smem_u32(Qb);
        #pragma unroll
        for (int i = 0; i < 10; i++) {
            int idx = tid + i * 256;
            int pl = idx / 1280, rem = idx % 1280;
            int r = rem / 10, c = rem % 10;
            CP_ASYNC16(qs + pl * QPL + (uint32_t)(r * QSTR + c * 8) * 2,
                       gq[pl] + ((size_t)head * SEQ + qbase + r) * HEAD_DIM + c * 8);
        }
        CP_COMMIT();
    }
    if (tid < AQ) {
        int i = qbase + tid;
        int s = 0;
        for (int j = 1; j < ncu; j++) s += (cu[j] <= i);
        segq[tid] = s;
    }
    __syncthreads();
    if (tid == 0) {
        int smin = segq[0], smax = segq[AQ - 1];
        for (int r = 1; r < AQ; r++) { smin = min(smin, segq[r]); smax = max(smax, segq[r]); }
        int lo = cu[smin], hi = cu[smax + 1];
        range[0] = lo;
        range[1] = hi;
        range[2] = (smin == smax) && (((hi - lo) % AK) == 0);
    }
    __syncthreads();
    const int lo = range[0], hi_ = range[1];
    const bool nomask = (range[2] != 0);

    auto load_kv = [&](int kt, int st) {
        const uint32_t ks = smem_u32(Kb) + st * KSTG;
        const uint32_t vs = smem_u32(Vb) + st * VSTG;
        #pragma unroll
        for (int i = 0; i < 5; i++) {
            int idx = tid + i * 256;
            if (idx < 640) {
                int pl = idx / 320, rem = idx % 320;
                int r = rem / 10, c = rem % 10;
                int row = min(kt + r, SEQ - 1);
                CP_ASYNC16(ks + pl * KPL + (uint32_t)(r * QSTR + c * 8) * 2,
                           gk[pl] + ((size_t)head * SEQ + row) * HEAD_DIM + c * 8);
            } else {
                int j = idx - 640;
                int pl = j / 320, rem = j % 320;
                int d = rem / 4, c = rem % 4;
                int col = min(kt + c * 8, SEQ - 8);
                CP_ASYNC16(vs + pl * VPL + (uint32_t)(d * VSTR + c * 8) * 2,
                           gv[pl] + ((size_t)head * HEAD_DIM + d) * SEQ + col);
            }
        }
        CP_COMMIT();
    };

    const int qr = ln >> 2;
    const int kq = (ln & 3) * 2;
    const int row0 = w * 16 + qr;
    const int row1 = row0 + 8;
    const int sq0 = segq[row0], sq1 = segq[row1];

    float m0 = -1e30f, m1 = -1e30f, l0 = 0.f, l1 = 0.f;
    float acc[10][4];
    #pragma unroll
    for (int n = 0; n < 10; n++)
        #pragma unroll
        for (int c = 0; c < 4; c++) acc[n][c] = 0.f;

    const int a_row = (ln & 15);
    const int a_kof = (ln < 16) ? 0 : 8;
    const int b_row = (ln & 7);
    const int b_kof = (ln & 8);

    load_kv(lo, 0);
    CP_WAIT(0);
    __syncthreads();

    int st = 0;
    for (int kt = lo; kt < hi_; kt += AK) {
        const bool hasNext = (kt + AK) < hi_;
        if (hasNext) load_kv(kt + AK, st ^ 1);

        if (!nomask && tid < AK) {
            int key = kt + tid;
            int s = -1;
            if (key < hi_) {
                s = 0;
                for (int j = 1; j < ncu; j++) s += (cu[j] <= key);
            }
            segk[st * AK + tid] = s;
        }
        if (hasNext) { CP_WAIT(1); } else { CP_WAIT(0); }
        __syncthreads();

        const uint32_t pQh = smem_u32(Qb);
        const uint32_t pQl = pQh + QPL;
        const uint32_t pKh = smem_u32(Kb) + st * KSTG;
        const uint32_t pKl = pKh + KPL;
        const uint32_t pVh = smem_u32(Vb) + st * VSTG;
        const uint32_t pVl = pVh + VPL;
        const int* sk = segk + st * AK;

        // ---- S = Q @ K^T, 3-term ----
        float S[4][4];
        #pragma unroll
        for (int j = 0; j < 4; j++)
            #pragma unroll
            for (int c = 0; c < 4; c++) S[j][c] = 0.f;

        #pragma unroll
        for (int kc = 0; kc < 5; kc++) {
            uint32_t ah[4], al[4];
            uint32_t qoff = (uint32_t)((w * 16 + a_row) * QSTR + kc * 16 + a_kof) * 2;
            LDSM_X4(ah[0], ah[1], ah[2], ah[3], pQh + qoff);
            LDSM_X4(al[0], al[1], al[2], al[3], pQl + qoff);
            uint32_t bh[4][2], bl[4][2];
            #pragma unroll
            for (int q = 0; q < 4; q++) {
                uint32_t koff = (uint32_t)((q * 8 + b_row) * QSTR
                                           + kc * 16 + b_kof) * 2;
                LDSM_X2(bh[q][0], bh[q][1], pKh + koff);
                LDSM_X2(bl[q][0], bl[q][1], pKl + koff);
            }
            #pragma unroll
            for (int q = 0; q < 4; q++)
                MMA16816(S[q][0], S[q][1], S[q][2], S[q][3],
                         ah[0], ah[1], ah[2], ah[3], bh[q][0], bh[q][1]);
            #pragma unroll
            for (int q = 0; q < 4; q++)
                MMA16816(S[q][0], S[q][1], S[q][2], S[q][3],
                         ah[0], ah[1], ah[2], ah[3], bl[q][0], bl[q][1]);
            #pragma unroll
            for (int q = 0; q < 4; q++)
                MMA16816(S[q][0], S[q][1], S[q][2], S[q][3],
                         al[0], al[1], al[2], al[3], bh[q][0], bh[q][1]);
        }

        // ---- online softmax (fast unmasked path / masked path) ----
        float mt0 = -1e30f, mt1 = -1e30f;
        float rs0 = 0.f, rs1 = 0.f;
        if (nomask) {
            #pragma unroll
            for (int j = 0; j < 4; j++) {
                mt0 = fmaxf(mt0, fmaxf(S[j][0], S[j][1]));
                mt1 = fmaxf(mt1, fmaxf(S[j][2], S[j][3]));
            }
            #pragma unroll
            for (int msk = 1; msk <= 2; msk <<= 1) {
                mt0 = fmaxf(mt0, __shfl_xor_sync(0xffffffffu, mt0, msk));
                mt1 = fmaxf(mt1, __shfl_xor_sync(0xffffffffu, mt1, msk));
            }
            float mn0 = fmaxf(m0, mt0), mn1 = fmaxf(m1, mt1);
            float alpha0 = __expf(m0 - mn0), alpha1 = __expf(m1 - mn1);
            #pragma unroll
            for (int j = 0; j < 4; j++) {
                float p0 = __expf(S[j][0] - mn0);
                float p1 = __expf(S[j][1] - mn0);
                float p2 = __expf(S[j][2] - mn1);
                float p3 = __expf(S[j][3] - mn1);
                S[j][0] = p0; S[j][1] = p1; S[j][2] = p2; S[j][3] = p3;
                rs0 += p0 + p1;
                rs1 += p2 + p3;
            }
            #pragma unroll
            for (int msk = 1; msk <= 2; msk <<= 1) {
                rs0 += __shfl_xor_sync(0xffffffffu, rs0, msk);
                rs1 += __shfl_xor_sync(0xffffffffu, rs1, msk);
            }
            l0 = l0 * alpha0 + rs0;
            l1 = l1 * alpha1 + rs1;
            m0 = mn0; m1 = mn1;
            #pragma unroll
            for (int n = 0; n < 10; n++) {
                acc[n][0] *= alpha0; acc[n][1] *= alpha0;
                acc[n][2] *= alpha1; acc[n][3] *= alpha1;
            }
        } else {
            #pragma unroll
            for (int j = 0; j < 4; j++) {
                int k0 = j * 8 + kq;
                int sk0 = sk[k0], sk1 = sk[k0 + 1];
                mt0 = fmaxf(mt0, (sk0 == sq0) ? S[j][0] : -1e30f);
                mt0 = fmaxf(mt0, (sk1 == sq0) ? S[j][1] : -1e30f);
                mt1 = fmaxf(mt1, (sk0 == sq1) ? S[j][2] : -1e30f);
                mt1 = fmaxf(mt1, (sk1 == sq1) ? S[j][3] : -1e30f);
            }
            #pragma unroll
            for (int msk = 1; msk <= 2; msk <<= 1) {
                mt0 = fmaxf(mt0, __shfl_xor_sync(0xffffffffu, mt0, msk));
                mt1 = fmaxf(mt1, __shfl_xor_sync(0xffffffffu, mt1, msk));
            }
            float mn0 = fmaxf(m0, mt0), mn1 = fmaxf(m1, mt1);
            float alpha0 = __expf(m0 - mn0), alpha1 = __expf(m1 - mn1);
            #pragma unroll
            for (int j = 0; j < 4; j++) {
                int k0 = j * 8 + kq;
                int sk0 = sk[k0], sk1 = sk[k0 + 1];
                float p0 = (sk0 == sq0) ? __expf(S[j][0] - mn0) : 0.f;
                float p1 = (sk1 == sq0) ? __expf(S[j][1] - mn0) : 0.f;
                float p2 = (sk0 == sq1) ? __expf(S[j][2] - mn1) : 0.f;
                float p3 = (sk1 == sq1) ? __expf(S[j][3] - mn1) : 0.f;
                S[j][0] = p0; S[j][1] = p1; S[j][2] = p2; S[j][3] = p3;
                rs0 += p0 + p1;
                rs1 += p2 + p3;
            }
            #pragma unroll
            for (int msk = 1; msk <= 2; msk <<= 1) {
                rs0 += __shfl_xor_sync(0xffffffffu, rs0, msk);
                rs1 += __shfl_xor_sync(0xffffffffu, rs1, msk);
            }
            l0 = l0 * alpha0 + rs0;
            l1 = l1 * alpha1 + rs1;
            m0 = mn0; m1 = mn1;
            #pragma unroll
            for (int n = 0; n < 10; n++) {
                acc[n][0] *= alpha0; acc[n][1] *= alpha0;
                acc[n][2] *= alpha1; acc[n][3] *= alpha1;
            }
        }

        // ---- O += P @ V, 3-term ----
        #pragma unroll
        for (int jc = 0; jc < 2; jc++) {
            float h00 = __bfloat162float(__float2bfloat16(S[2*jc][0]));
            float h01 = __bfloat162float(__float2bfloat16(S[2*jc][1]));
            float h02 = __bfloat162float(__float2bfloat16(S[2*jc][2]));
            float h03 = __bfloat162float(__float2bfloat16(S[2*jc][3]));
            float h10 = __bfloat162float(__float2bfloat16(S[2*jc+1][0]));
            float h11 = __bfloat162float(__float2bfloat16(S[2*jc+1][1]));
            float h12 = __bfloat162float(__float2bfloat16(S[2*jc+1][2]));
            float h13 = __bfloat162float(__float2bfloat16(S[2*jc+1][3]));
            uint32_t aPh[4], aPl[4];
            aPh[0] = pack_bf2(h00, h01);
            aPh[1] = pack_bf2(h02, h03);
            aPh[2] = pack_bf2(h10, h11);
            aPh[3] = pack_bf2(h12, h13);
            aPl[0] = pack_bf2(S[2*jc][0] - h00, S[2*jc][1] - h01);
            aPl[1] = pack_bf2(S[2*jc][2] - h02, S[2*jc][3] - h03);
            aPl[2] = pack_bf2(S[2*jc+1][0] - h10, S[2*jc+1][1] - h11);
            aPl[3] = pack_bf2(S[2*jc+1][2] - h12, S[2*jc+1][3] - h13);

            #pragma unroll
            for (int ng = 0; ng < 3; ng++) {
                const int gs = ng * 4;
                const int gn = (ng == 2) ? 2 : 4;
                uint32_t bh[4][2], bl[4][2];
                #pragma unroll
                for (int q = 0; q < 4; q++) {
                    if (q < gn) {
                        uint32_t voff = (uint32_t)(((gs + q) * 8 + b_row) * VSTR
                                                   + jc * 16 + b_kof) * 2;
                        LDSM_X2(bh[q][0], bh[q][1], pVh + voff);
                        LDSM_X2(bl[q][0], bl[q][1], pVl + voff);
                    }
                }
                #pragma unroll
                for (int q = 0; q < 4; q++)
                    if (q < gn)
                        MMA16816(acc[gs+q][0], acc[gs+q][1], acc[gs+q][2], acc[gs+q][3],
                                 aPh[0], aPh[1], aPh[2], aPh[3], bh[q][0], bh[q][1]);
                #pragma unroll
                for (int q = 0; q < 4; q++)
                    if (q < gn)
                        MMA16816(acc[gs+q][0], acc[gs+q][1], acc[gs+q][2], acc[gs+q][3],
                                 aPh[0], aPh[1], aPh[2], aPh[3], bl[q][0], bl[q][1]);
                #pragma unroll
                for (int q = 0; q < 4; q++)
                    if (q < gn)
                        MMA16816(acc[gs+q][0], acc[gs+q][1], acc[gs+q][2], acc[gs+q][3],
                                 aPl[0], aPl[1], aPl[2], aPl[3], bh[q][0], bh[q][1]);
            }
        }

        __syncthreads();
        st ^= 1;
    }

    float il0 = (l0 > 0.f) ? (1.f / l0) : 0.f;
    float il1 = (l1 > 0.f) ? (1.f / l1) : 0.f;
    #pragma unroll
    for (int n = 0; n < 10; n++) {
        int d = n * 8 + kq;
        size_t o0 = (size_t)(qbase + row0) * DIM + head * HEAD_DIM + d;
        size_t o1 = (size_t)(qbase + row1) * DIM + head * HEAD_DIM + d;
        *(uint32_t*)&g_at_h[o0] = pack_h2(acc[n][0] * il0, acc[n][1] * il0);
        *(uint32_t*)&g_at_h[o1] = pack_h2(acc[n][2] * il1, acc[n][3] * il1);
    }
}

// ---------------------------------------------------------------------------
extern "C" void kernel_launch(void* const* d_in, const int* in_sizes, int n_in,
                              void* d_out, int out_size)
{
    const float* hidden = (const float*)d_in[0];
    const float* rotary = (const float*)d_in[1];
    const int*   cu     = (const int*)d_in[2];
    const float* qkv_w  = (const float*)d_in[3];
    const float* qkv_b  = (const float*)d_in[4];
    const float* proj_w = (const float*)d_in[5];
    const float* proj_b = (const float*)d_in[6];
    float* out = (float*)d_out;
    int ncu = in_sizes[2];

    float *qkv_ptr;
    __half *hidH, *wqH, *wqL, *wpH, *wpL, *atH;
    cudaGetSymbolAddress((void**)&qkv_ptr, g_qkv);
    cudaGetSymbolAddress((void**)&hidH, g_hid_h);
    cudaGetSymbolAddress((void**)&wqH, g_wq_h);
    cudaGetSymbolAddress((void**)&wqL, g_wq_l);
    cudaGetSymbolAddress((void**)&wpH, g_wp_h);
    cudaGetSymbolAddress((void**)&wpL, g_wp_l);
    cudaGetSymbolAddress((void**)&atH, g_at_h);

    cudaFuncSetAttribute(hgemm2_kernel,
                         cudaFuncAttributeMaxDynamicSharedMemorySize, HG_SMEM);

    // 0) Merged decomposition
    {
        int total = HID4 + WQ4 + WP4;
        decomp_all_kernel<<<(total + 255) / 256, 256>>>(
            (const float4*)hidden, (const float4*)qkv_w, (const float4*)proj_w,
            (uint32_t*)hidH, (uint32_t*)wqH, (uint32_t*)wqL,
            (uint32_t*)wpH, (uint32_t*)wpL);
    }

    // 1) QKV GEMM
    hgemm2_kernel<<<dim3(QKV_DIM / 64, SEQ / 128), 256, HG_SMEM>>>(
        hidH, wqH, wqL, qkv_b, qkv_ptr, SEQ, QKV_DIM, DIM);

    // 2) Merged Q/K/V prep
    prep_kernel<<<dim3(SEQ / 64, HEADS + 1), 256>>>(rotary);

    // 3) Flash attention (unmasked fast path)
    {
        cudaFuncSetAttribute(fattn_kernel,
                             cudaFuncAttributeMaxDynamicSharedMemorySize, FA_SMEM);
        fattn_kernel<<<dim3(SEQ / AQ, HEADS), 256, FA_SMEM>>>(cu, ncu);
    }

    // 4) proj GEMM
    hgemm2_kernel<<<dim3(DIM / 64, SEQ / 128), 256, HG_SMEM>>>(
        atH, wpH, wpL, proj_b, out, SEQ, DIM, DIM);
}

// round 14
// speedup vs baseline: 1.2307x; 1.2307x over previous
#include <cuda_runtime.h>
#include <cuda_bf16.h>
#include <cuda_fp16.h>
#include <math.h>
#include <stdint.h>

#define SEQ      2048
#define DIM      1280
#define HEADS    16
#define HEAD_DIM 80
#define QKV_DIM  3840

// ---------------------------------------------------------------------------
// Scratch
// ---------------------------------------------------------------------------
__device__ float g_qkv[SEQ * QKV_DIM];
__device__ __half g_hid_h[SEQ * DIM];
__device__ __half g_wq_h[QKV_DIM * DIM], g_wq_l[QKV_DIM * DIM];
__device__ __half g_wp_h[DIM * DIM],     g_wp_l[DIM * DIM];
__device__ __half g_at_h[SEQ * DIM];
__device__ __nv_bfloat16 g_q_h[HEADS * SEQ * HEAD_DIM], g_q_l[HEADS * SEQ * HEAD_DIM];
__device__ __nv_bfloat16 g_k_h[HEADS * SEQ * HEAD_DIM], g_k_l[HEADS * SEQ * HEAD_DIM];
__device__ __nv_bfloat16 g_vt_h[HEADS * HEAD_DIM * SEQ], g_vt_l[HEADS * HEAD_DIM * SEQ];

// ---------------------------------------------------------------------------
// PTX helpers
// ---------------------------------------------------------------------------
#define CP_ASYNC16(dst, src) \
    asm volatile("cp.async.cg.shared.global [%0], [%1], 16;" :: "r"(dst), "l"(src))
#define CP_COMMIT() asm volatile("cp.async.commit_group;")
#define CP_WAIT(n)  asm volatile("cp.async.wait_group %0;" :: "n"(n))

#define LDSM_X4(r0,r1,r2,r3,addr) \
    asm volatile("ldmatrix.sync.aligned.m8n8.x4.shared.b16 {%0,%1,%2,%3}, [%4];" \
        : "=r"(r0),"=r"(r1),"=r"(r2),"=r"(r3) : "r"(addr))
#define LDSM_X2(r0,r1,addr) \
    asm volatile("ldmatrix.sync.aligned.m8n8.x2.shared.b16 {%0,%1}, [%2];" \
        : "=r"(r0),"=r"(r1) : "r"(addr))

#define MMA16816(c0,c1,c2,c3,a0,a1,a2,a3,b0,b1) \
    asm volatile("mma.sync.aligned.m16n8k16.row.col.f32.bf16.bf16.f32 " \
        "{%0,%1,%2,%3}, {%4,%5,%6,%7}, {%8,%9}, {%0,%1,%2,%3};" \
        : "+f"(c0),"+f"(c1),"+f"(c2),"+f"(c3) \
        : "r"(a0),"r"(a1),"r"(a2),"r"(a3),"r"(b0),"r"(b1))

#define MMAH16816(c0,c1,c2,c3,a0,a1,a2,a3,b0,b1) \
    asm volatile("mma.sync.aligned.m16n8k16.row.col.f32.f16.f16.f32 " \
        "{%0,%1,%2,%3}, {%4,%5,%6,%7}, {%8,%9}, {%0,%1,%2,%3};" \
        : "+f"(c0),"+f"(c1),"+f"(c2),"+f"(c3) \
        : "r"(a0),"r"(a1),"r"(a2),"r"(a3),"r"(b0),"r"(b1))

__device__ __forceinline__ uint32_t smem_u32(const void* p) {
    return (uint32_t)__cvta_generic_to_shared(p);
}
__device__ __forceinline__ uint32_t pack_bf2(float a, float b) {
    __nv_bfloat162 v = __float22bfloat162_rn(make_float2(a, b));
    return *(uint32_t*)&v;
}
__device__ __forceinline__ uint32_t pack_h2(float a, float b) {
    __half2 v = __floats2half2_rn(a, b);
    return *(uint32_t*)&v;
}

// ---------------------------------------------------------------------------
// fp16 2-term HGEMM (round-10, at HMMA roofline — unchanged)
// ---------------------------------------------------------------------------
#define KBLK 32
#define KPAD 40
#define APLANE_B (128 * KPAD * 2)
#define BPLANE_B (64 * KPAD * 2)
#define STAGE_B (APLANE_B + 2 * BPLANE_B)
#define HG_SMEM (2 * STAGE_B)

__global__ void __launch_bounds__(256, 3) hgemm2_kernel(
    const __half* __restrict__ Ah_,
    const __half* __restrict__ Bh_, const __half* __restrict__ Bl_,
    const float* __restrict__ bias, float* __restrict__ C,
    int M, int N, int K)
{
    extern __shared__ char smraw[];
    const uint32_t sb = smem_u32(smraw);

    const int tid = threadIdx.x;
    const int ln  = tid & 31;
    const int wid = tid >> 5;
    const int wm  = wid >> 1;
    const int wn  = wid & 1;
    const int m0  = blockIdx.y * 128;
    const int n0  = blockIdx.x * 64;

    const __half* gA = Ah_ + (size_t)m0 * K;
    const __half* gB[2] = { Bh_ + (size_t)n0 * K, Bl_ + (size_t)n0 * K };

    const int arow0 = tid >> 2;
    const int arow1 = (tid + 256) >> 2;
    const int brow  = tid >> 2;
    const int kc16  = (tid & 3) * 8;

    auto load_stage = [&](int kt, int s) {
        const uint32_t stb = sb + s * STAGE_B;
        CP_ASYNC16(stb + (uint32_t)(arow0 * KPAD + kc16) * 2,
                   gA + (size_t)arow0 * K + kt + kc16);
        CP_ASYNC16(stb + (uint32_t)(arow1 * KPAD + kc16) * 2,
                   gA + (size_t)arow1 * K + kt + kc16);
        #pragma unroll
        for (int p = 0; p < 2; p++) {
            const uint32_t pb = stb + APLANE_B + p * BPLANE_B;
            CP_ASYNC16(pb + (uint32_t)(brow * KPAD + kc16) * 2,
                       gB[p] + (size_t)brow * K + kt + kc16);
        }
        CP_COMMIT();
    };

    float acc[2][4][4];
    #pragma unroll
    for (int mi = 0; mi < 2; mi++)
        #pragma unroll
        for (int ni = 0; ni < 4; ni++)
            #pragma unroll
            for (int c = 0; c < 4; c++) acc[mi][ni][c] = 0.f;

    load_stage(0, 0);
    CP_WAIT(0);
    __syncthreads();

    const int a_row = (ln & 15);
    const int a_kof = (ln < 16) ? 0 : 8;
    const int b_row = (ln & 7);
    const int b_kof = (ln & 8);

    int buf = 0;
    for (int kt = 0; kt < K; kt += KBLK) {
        const bool hasNext = (kt + KBLK) < K;
        if (hasNext) load_stage(kt + KBLK, buf ^ 1);

        const uint32_t stb = sb + buf * STAGE_B;
        const uint32_t pAh = stb;
        const uint32_t pBh = stb + APLANE_B;
        const uint32_t pBl = stb + APLANE_B + BPLANE_B;

        #pragma unroll
        for (int ks = 0; ks < 2; ks++) {
            const int k0 = ks * 16;
            uint32_t ah[2][4];
            #pragma unroll
            for (int mi = 0; mi < 2; mi++) {
                uint32_t off = (uint32_t)((wm * 32 + mi * 16 + a_row) * KPAD
                                          + k0 + a_kof) * 2;
                LDSM_X4(ah[mi][0], ah[mi][1], ah[mi][2], ah[mi][3], pAh + off);
            }
            uint32_t bh[4][2], bl[4][2];
            #pragma unroll
            for (int ni = 0; ni < 4; ni++) {
                uint32_t off = (uint32_t)((wn * 32 + ni * 8 + b_row) * KPAD
                                          + k0 + b_kof) * 2;
                LDSM_X2(bh[ni][0], bh[ni][1], pBh + off);
                LDSM_X2(bl[ni][0], bl[ni][1], pBl + off);
            }
            #pragma unroll
            for (int ni = 0; ni < 4; ni++)
                #pragma unroll
                for (int mi = 0; mi < 2; mi++)
                    MMAH16816(acc[mi][ni][0], acc[mi][ni][1],
                              acc[mi][ni][2], acc[mi][ni][3],
                              ah[mi][0], ah[mi][1], ah[mi][2], ah[mi][3],
                              bh[ni][0], bh[ni][1]);
            #pragma unroll
            for (int ni = 0; ni < 4; ni++)
                #pragma unroll
                for (int mi = 0; mi < 2; mi++)
                    MMAH16816(acc[mi][ni][0], acc[mi][ni][1],
                              acc[mi][ni][2], acc[mi][ni][3],
                              ah[mi][0], ah[mi][1], ah[mi][2], ah[mi][3],
                              bl[ni][0], bl[ni][1]);
        }

        if (hasNext) {
            CP_WAIT(0);
            __syncthreads();
            buf ^= 1;
        }
    }

    const int crow = ln >> 2;
    const int ccol = (ln & 3) * 2;
    #pragma unroll
    for (int mi = 0; mi < 2; mi++) {
        #pragma unroll
        for (int ni = 0; ni < 4; ni++) {
            int col = n0 + wn * 32 + ni * 8 + ccol;
            float b0 = bias[col], b1 = bias[col + 1];
            int r0 = m0 + wm * 32 + mi * 16 + crow;
            float2 v0 = make_float2(acc[mi][ni][0] + b0, acc[mi][ni][1] + b1);
            float2 v1 = make_float2(acc[mi][ni][2] + b0, acc[mi][ni][3] + b1);
            *(float2*)(C + (size_t)r0 * N + col)       = v0;
            *(float2*)(C + (size_t)(r0 + 8) * N + col) = v1;
        }
    }
}

// ---------------------------------------------------------------------------
// Merged decompose: hidden (hi only) + qkv_w (hi/lo) + proj_w (hi/lo)
// ---------------------------------------------------------------------------
#define HID4 (SEQ * DIM / 4)
#define WQ4  (QKV_DIM * DIM / 4)
#define WP4  (DIM * DIM / 4)

__global__ void __launch_bounds__(256) decomp_all_kernel(
    const float4* __restrict__ hid, const float4* __restrict__ wq,
    const float4* __restrict__ wp,
    uint32_t* __restrict__ hidH,
    uint32_t* __restrict__ wqH, uint32_t* __restrict__ wqL,
    uint32_t* __restrict__ wpH, uint32_t* __restrict__ wpL)
{
    int idx = blockIdx.x * blockDim.x + threadIdx.x;
    if (idx < HID4) {
        float4 v = hid[idx];
        hidH[idx * 2]     = pack_h2(v.x, v.y);
        hidH[idx * 2 + 1] = pack_h2(v.z, v.w);
        return;
    }
    const float4* src;
    uint32_t *dh, *dl;
    int j;
    if (idx < HID4 + WQ4) {
        j = idx - HID4;  src = wq; dh = wqH; dl = wqL;
    } else if (idx < HID4 + WQ4 + WP4) {
        j = idx - HID4 - WQ4;  src = wp; dh = wpH; dl = wpL;
    } else return;

    float4 v = src[j];
    __half h0 = __float2half_rn(v.x);
    __half h1 = __float2half_rn(v.y);
    __half h2 = __float2half_rn(v.z);
    __half h3 = __float2half_rn(v.w);
    dh[j * 2]     = pack_h2(v.x, v.y);
    dh[j * 2 + 1] = pack_h2(v.z, v.w);
    dl[j * 2]     = pack_h2(v.x - __half2float(h0), v.y - __half2float(h1));
    dl[j * 2 + 1] = pack_h2(v.z - __half2float(h2), v.w - __half2float(h3));
}

// ---------------------------------------------------------------------------
// Q/K prep: sincos once per (s,d2), reused across 16 heads (320 blocks)
// ---------------------------------------------------------------------------
__global__ void __launch_bounds__(256) qkprep_kernel(const float* __restrict__ rot)
{
    int t = blockIdx.x * blockDim.x + threadIdx.x;
    if (t >= SEQ * 40) return;
    int d2 = t % 40;
    int s  = t / 40;

    float f = rot[s * 40 + d2];
    float si, co;
    sincosf(f, &si, &co);
    const float scale = rsqrtf((float)HEAD_DIM);

    #pragma unroll 4
    for (int h = 0; h < HEADS; h++) {
        size_t qb = (size_t)s * QKV_DIM + h * HEAD_DIM;
        float q1 = g_qkv[qb + d2],        q2 = g_qkv[qb + 40 + d2];
        float k1 = g_qkv[qb + DIM + d2],  k2 = g_qkv[qb + DIM + 40 + d2];

        float qr1 = (q1 * co - q2 * si) * scale;
        float qr2 = (q2 * co + q1 * si) * scale;
        float kr1 = k1 * co - k2 * si;
        float kr2 = k2 * co + k1 * si;

        size_t ob = ((size_t)h * SEQ + s) * HEAD_DIM;
        __nv_bfloat16 hq1 = __float2bfloat16(qr1);
        __nv_bfloat16 hq2 = __float2bfloat16(qr2);
        __nv_bfloat16 hk1 = __float2bfloat16(kr1);
        __nv_bfloat16 hk2 = __float2bfloat16(kr2);
        g_q_h[ob + d2]      = hq1;
        g_q_h[ob + 40 + d2] = hq2;
        g_q_l[ob + d2]      = __float2bfloat16(qr1 - __bfloat162float(hq1));
        g_q_l[ob + 40 + d2] = __float2bfloat16(qr2 - __bfloat162float(hq2));
        g_k_h[ob + d2]      = hk1;
        g_k_h[ob + 40 + d2] = hk2;
        g_k_l[ob + d2]      = __float2bfloat16(kr1 - __bfloat162float(hk1));
        g_k_l[ob + 40 + d2] = __float2bfloat16(kr2 - __bfloat162float(hk2));
    }
}

// ---------------------------------------------------------------------------
// V prep: transpose + bf16 hi/lo decomp -> [h][d][s] planes (512 blocks)
// ---------------------------------------------------------------------------
__global__ void __launch_bounds__(256) vtprep_kernel()
{
    __shared__ float T[HEAD_DIM][65];
    const int tid = threadIdx.x;
    const int s0  = blockIdx.x * 64;
    const int h   = blockIdx.y;

    #pragma unroll
    for (int i = 0; i < 20; i++) {
        int idx = tid + i * 256;
        int r = idx / HEAD_DIM, d = idx % HEAD_DIM;
        T[d][r] = g_qkv[(size_t)(s0 + r) * QKV_DIM + 2 * DIM + h * HEAD_DIM + d];
    }
    __syncthreads();
    #pragma unroll
    for (int i = 0; i < 20; i++) {
        int idx = tid + i * 256;
        int d = idx / 64, r = idx % 64;
        float v = T[d][r];
        __nv_bfloat16 hi = __float2bfloat16(v);
        size_t o = ((size_t)h * HEAD_DIM + d) * SEQ + s0 + r;
        g_vt_h[o] = hi;
        g_vt_l[o] = __float2bfloat16(v - __bfloat162float(hi));
    }
}

// ---------------------------------------------------------------------------
// Tensor-core flash attention: AK=32, 2 CTAs/SM, unmasked fast path (round-13)
// ---------------------------------------------------------------------------
#define AQ    128
#define AK    32
#define QSTR  88
#define VSTR  40
#define QPL   (AQ * QSTR * 2)
#define KPL   (AK * QSTR * 2)
#define VPL   (HEAD_DIM * VSTR * 2)
#define KSTG  (2 * KPL)
#define VSTG  (2 * VPL)
#define FA_SMEM (2*QPL + 2*KSTG + 2*VSTG + (AQ + 2*AK + 8) * 4)

__global__ void __launch_bounds__(256, 2) fattn_kernel(const int* __restrict__ cu, int ncu)
{
    extern __shared__ char smraw[];
    char* Qb  = smraw;
    char* Kb  = Qb + 2 * QPL;
    char* Vb  = Kb + 2 * KSTG;
    int* segq  = (int*)(Vb + 2 * VSTG);
    int* segk  = segq + AQ;
    int* range = segk + 2 * AK;        // [0]=lo [1]=hi [2]=nomask

    const int tid = threadIdx.x;
    const int w   = tid >> 5;
    const int ln  = tid & 31;
    const int head  = blockIdx.y;
    const int qbase = blockIdx.x * AQ;

    const __nv_bfloat16* gq[2] = { g_q_h, g_q_l };
    const __nv_bfloat16* gk[2] = { g_k_h, g_k_l };
    const __nv_bfloat16* gv[2] = { g_vt_h, g_vt_l };

    {
        const uint32_t qs = smem_u32(Qb);
        #pragma unroll
        for (int i = 0; i < 10; i++) {
            int idx = tid + i * 256;
            int pl = idx / 1280, rem = idx % 1280;
            int r = rem / 10, c = rem % 10;
            CP_ASYNC16(qs + pl * QPL + (uint32_t)(r * QSTR + c * 8) * 2,
                       gq[pl] + ((size_t)head * SEQ + qbase + r) * HEAD_DIM + c * 8);
        }
        CP_COMMIT();
    }
    if (tid < AQ) {
        int i = qbase + tid;
        int s = 0;
        for (int j = 1; j < ncu; j++) s += (cu[j] <= i);
        segq[tid] = s;
    }
    __syncthreads();
    if (tid == 0) {
        int smin = segq[0], smax = segq[AQ - 1];
        for (int r = 1; r < AQ; r++) { smin = min(smin, segq[r]); smax = max(smax, segq[r]); }
        int lo = cu[smin], hi = cu[smax + 1];
        range[0] = lo;
        range[1] = hi;
        range[2] = (smin == smax) && (((hi - lo) % AK) == 0);
    }
    __syncthreads();
    const int lo = range[0], hi_ = range[1];
    const bool nomask = (range[2] != 0);

    auto load_kv = [&](int kt, int st) {
        const uint32_t ks = smem_u32(Kb) + st * KSTG;
        const uint32_t vs = smem_u32(Vb) + st * VSTG;
        #pragma unroll
        for (int i = 0; i < 5; i++) {
            int idx = tid + i * 256;
            if (idx < 640) {
                int pl = idx / 320, rem = idx % 320;
                int r = rem / 10, c = rem % 10;
                int row = min(kt + r, SEQ - 1);
                CP_ASYNC16(ks + pl * KPL + (uint32_t)(r * QSTR + c * 8) * 2,
                           gk[pl] + ((size_t)head * SEQ + row) * HEAD_DIM + c * 8);
            } else {
                int j = idx - 640;
                int pl = j / 320, rem = j % 320;
                int d = rem / 4, c = rem % 4;
                int col = min(kt + c * 8, SEQ - 8);
                CP_ASYNC16(vs + pl * VPL + (uint32_t)(d * VSTR + c * 8) * 2,
                           gv[pl] + ((size_t)head * HEAD_DIM + d) * SEQ + col);
            }
        }
        CP_COMMIT();
    };

    const int qr = ln >> 2;
    const int kq = (ln & 3) * 2;
    const int row0 = w * 16 + qr;
    const int row1 = row0 + 8;
    const int sq0 = segq[row0], sq1 = segq[row1];

    float m0 = -1e30f, m1 = -1e30f, l0 = 0.f, l1 = 0.f;
    float acc[10][4];
    #pragma unroll
    for (int n = 0; n < 10; n++)
        #pragma unroll
        for (int c = 0; c < 4; c++) acc[n][c] = 0.f;

    const int a_row = (ln & 15);
    const int a_kof = (ln < 16) ? 0 : 8;
    const int b_row = (ln & 7);
    const int b_kof = (ln & 8);

    load_kv(lo, 0);
    CP_WAIT(0);
    __syncthreads();

    int st = 0;
    for (int kt = lo; kt < hi_; kt += AK) {
        const bool hasNext = (kt + AK) < hi_;
        if (hasNext) load_kv(kt + AK, st ^ 1);

        if (!nomask && tid < AK) {
            int key = kt + tid;
            int s = -1;
            if (key < hi_) {
                s = 0;
                for (int j = 1; j < ncu; j++) s += (cu[j] <= key);
            }
            segk[st * AK + tid] = s;
        }
        if (hasNext) { CP_WAIT(1); } else { CP_WAIT(0); }
        __syncthreads();

        const uint32_t pQh = smem_u32(Qb);
        const uint32_t pQl = pQh + QPL;
        const uint32_t pKh = smem_u32(Kb) + st * KSTG;
        const uint32_t pKl = pKh + KPL;
        const uint32_t pVh = smem_u32(Vb) + st * VSTG;
        const uint32_t pVl = pVh + VPL;
        const int* sk = segk + st * AK;

        // ---- S = Q @ K^T, 3-term ----
        float S[4][4];
        #pragma unroll
        for (int j = 0; j < 4; j++)
            #pragma unroll
            for (int c = 0; c < 4; c++) S[j][c] = 0.f;

        #pragma unroll
        for (int kc = 0; kc < 5; kc++) {
            uint32_t ah[4], al[4];
            uint32_t qoff = (uint32_t)((w * 16 + a_row) * QSTR + kc * 16 + a_kof) * 2;
            LDSM_X4(ah[0], ah[1], ah[2], ah[3], pQh + qoff);
            LDSM_X4(al[0], al[1], al[2], al[3], pQl + qoff);
            uint32_t bh[4][2], bl[4][2];
            #pragma unroll
            for (int q = 0; q < 4; q++) {
                uint32_t koff = (uint32_t)((q * 8 + b_row) * QSTR
                                           + kc * 16 + b_kof) * 2;
                LDSM_X2(bh[q][0], bh[q][1], pKh + koff);
                LDSM_X2(bl[q][0], bl[q][1], pKl + koff);
            }
            #pragma unroll
            for (int q = 0; q < 4; q++)
                MMA16816(S[q][0], S[q][1], S[q][2], S[q][3],
                         ah[0], ah[1], ah[2], ah[3], bh[q][0], bh[q][1]);
            #pragma unroll
            for (int q = 0; q < 4; q++)
                MMA16816(S[q][0], S[q][1], S[q][2], S[q][3],
                         ah[0], ah[1], ah[2], ah[3], bl[q][0], bl[q][1]);
            #pragma unroll
            for (int q = 0; q < 4; q++)
                MMA16816(S[q][0], S[q][1], S[q][2], S[q][3],
                         al[0], al[1], al[2], al[3], bh[q][0], bh[q][1]);
        }

        // ---- online softmax (fast unmasked path / masked path) ----
        float mt0 = -1e30f, mt1 = -1e30f;
        float rs0 = 0.f, rs1 = 0.f;
        if (nomask) {
            #pragma unroll
            for (int j = 0; j < 4; j++) {
                mt0 = fmaxf(mt0, fmaxf(S[j][0], S[j][1]));
                mt1 = fmaxf(mt1, fmaxf(S[j][2], S[j][3]));
            }
            #pragma unroll
            for (int msk = 1; msk <= 2; msk <<= 1) {
                mt0 = fmaxf(mt0, __shfl_xor_sync(0xffffffffu, mt0, msk));
                mt1 = fmaxf(mt1, __shfl_xor_sync(0xffffffffu, mt1, msk));
            }
            float mn0 = fmaxf(m0, mt0), mn1 = fmaxf(m1, mt1);
            float alpha0 = __expf(m0 - mn0), alpha1 = __expf(m1 - mn1);
            #pragma unroll
            for (int j = 0; j < 4; j++) {
                float p0 = __expf(S[j][0] - mn0);
                float p1 = __expf(S[j][1] - mn0);
                float p2 = __expf(S[j][2] - mn1);
                float p3 = __expf(S[j][3] - mn1);
                S[j][0] = p0; S[j][1] = p1; S[j][2] = p2; S[j][3] = p3;
                rs0 += p0 + p1;
                rs1 += p2 + p3;
            }
            #pragma unroll
            for (int msk = 1; msk <= 2; msk <<= 1) {
                rs0 += __shfl_xor_sync(0xffffffffu, rs0, msk);
                rs1 += __shfl_xor_sync(0xffffffffu, rs1, msk);
            }
            l0 = l0 * alpha0 + rs0;
            l1 = l1 * alpha1 + rs1;
            m0 = mn0; m1 = mn1;
            #pragma unroll
            for (int n = 0; n < 10; n++) {
                acc[n][0] *= alpha0; acc[n][1] *= alpha0;
                acc[n][2] *= alpha1; acc[n][3] *= alpha1;
            }
        } else {
            #pragma unroll
            for (int j = 0; j < 4; j++) {
                int k0 = j * 8 + kq;
                int sk0 = sk[k0], sk1 = sk[k0 + 1];
                mt0 = fmaxf(mt0, (sk0 == sq0) ? S[j][0] : -1e30f);
                mt0 = fmaxf(mt0, (sk1 == sq0) ? S[j][1] : -1e30f);
                mt1 = fmaxf(mt1, (sk0 == sq1) ? S[j][2] : -1e30f);
                mt1 = fmaxf(mt1, (sk1 == sq1) ? S[j][3] : -1e30f);
            }
            #pragma unroll
            for (int msk = 1; msk <= 2; msk <<= 1) {
                mt0 = fmaxf(mt0, __shfl_xor_sync(0xffffffffu, mt0, msk));
                mt1 = fmaxf(mt1, __shfl_xor_sync(0xffffffffu, mt1, msk));
            }
            float mn0 = fmaxf(m0, mt0), mn1 = fmaxf(m1, mt1);
            float alpha0 = __expf(m0 - mn0), alpha1 = __expf(m1 - mn1);
            #pragma unroll
            for (int j = 0; j < 4; j++) {
                int k0 = j * 8 + kq;
                int sk0 = sk[k0], sk1 = sk[k0 + 1];
                float p0 = (sk0 == sq0) ? __expf(S[j][0] - mn0) : 0.f;
                float p1 = (sk1 == sq0) ? __expf(S[j][1] - mn0) : 0.f;
                float p2 = (sk0 == sq1) ? __expf(S[j][2] - mn1) : 0.f;
                float p3 = (sk1 == sq1) ? __expf(S[j][3] - mn1) : 0.f;
                S[j][0] = p0; S[j][1] = p1; S[j][2] = p2; S[j][3] = p3;
                rs0 += p0 + p1;
                rs1 += p2 + p3;
            }
            #pragma unroll
            for (int msk = 1; msk <= 2; msk <<= 1) {
                rs0 += __shfl_xor_sync(0xffffffffu, rs0, msk);
                rs1 += __shfl_xor_sync(0xffffffffu, rs1, msk);
            }
            l0 = l0 * alpha0 + rs0;
            l1 = l1 * alpha1 + rs1;
            m0 = mn0; m1 = mn1;
            #pragma unroll
            for (int n = 0; n < 10; n++) {
                acc[n][0] *= alpha0; acc[n][1] *= alpha0;
                acc[n][2] *= alpha1; acc[n][3] *= alpha1;
            }
        }

        // ---- O += P @ V, 3-term ----
        #pragma unroll
        for (int jc = 0; jc < 2; jc++) {
            float h00 = __bfloat162float(__float2bfloat16(S[2*jc][0]));
            float h01 = __bfloat162float(__float2bfloat16(S[2*jc][1]));
            float h02 = __bfloat162float(__float2bfloat16(S[2*jc][2]));
            float h03 = __bfloat162float(__float2bfloat16(S[2*jc][3]));
            float h10 = __bfloat162float(__float2bfloat16(S[2*jc+1][0]));
            float h11 = __bfloat162float(__float2bfloat16(S[2*jc+1][1]));
            float h12 = __bfloat162float(__float2bfloat16(S[2*jc+1][2]));
            float h13 = __bfloat162float(__float2bfloat16(S[2*jc+1][3]));
            uint32_t aPh[4], aPl[4];
            aPh[0] = pack_bf2(h00, h01);
            aPh[1] = pack_bf2(h02, h03);
            aPh[2] = pack_bf2(h10, h11);
            aPh[3] = pack_bf2(h12, h13);
            aPl[0] = pack_bf2(S[2*jc][0] - h00, S[2*jc][1] - h01);
            aPl[1] = pack_bf2(S[2*jc][2] - h02, S[2*jc][3] - h03);
            aPl[2] = pack_bf2(S[2*jc+1][0] - h10, S[2*jc+1][1] - h11);
            aPl[3] = pack_bf2(S[2*jc+1][2] - h12, S[2*jc+1][3] - h13);

            #pragma unroll
            for (int ng = 0; ng < 3; ng++) {
                const int gs = ng * 4;
                const int gn = (ng == 2) ? 2 : 4;
                uint32_t bh[4][2], bl[4][2];
                #pragma unroll
                for (int q = 0; q < 4; q++) {
                    if (q < gn) {
                        uint32_t voff = (uint32_t)(((gs + q) * 8 + b_row) * VSTR
                                                   + jc * 16 + b_kof) * 2;
                        LDSM_X2(bh[q][0], bh[q][1], pVh + voff);
                        LDSM_X2(bl[q][0], bl[q][1], pVl + voff);
                    }
                }
                #pragma unroll
                for (int q = 0; q < 4; q++)
                    if (q < gn)
                        MMA16816(acc[gs+q][0], acc[gs+q][1], acc[gs+q][2], acc[gs+q][3],
                                 aPh[0], aPh[1], aPh[2], aPh[3], bh[q][0], bh[q][1]);
                #pragma unroll
                for (int q = 0; q < 4; q++)
                    if (q < gn)
                        MMA16816(acc[gs+q][0], acc[gs+q][1], acc[gs+q][2], acc[gs+q][3],
                                 aPh[0], aPh[1], aPh[2], aPh[3], bl[q][0], bl[q][1]);
                #pragma unroll
                for (int q = 0; q < 4; q++)
                    if (q < gn)
                        MMA16816(acc[gs+q][0], acc[gs+q][1], acc[gs+q][2], acc[gs+q][3],
                                 aPl[0], aPl[1], aPl[2], aPl[3], bh[q][0], bh[q][1]);
            }
        }

        __syncthreads();
        st ^= 1;
    }

    float il0 = (l0 > 0.f) ? (1.f / l0) : 0.f;
    float il1 = (l1 > 0.f) ? (1.f / l1) : 0.f;
    #pragma unroll
    for (int n = 0; n < 10; n++) {
        int d = n * 8 + kq;
        size_t o0 = (size_t)(qbase + row0) * DIM + head * HEAD_DIM + d;
        size_t o1 = (size_t)(qbase + row1) * DIM + head * HEAD_DIM + d;
        *(uint32_t*)&g_at_h[o0] = pack_h2(acc[n][0] * il0, acc[n][1] * il0);
        *(uint32_t*)&g_at_h[o1] = pack_h2(acc[n][2] * il1, acc[n][3] * il1);
    }
}

// ---------------------------------------------------------------------------
extern "C" void kernel_launch(void* const* d_in, const int* in_sizes, int n_in,
                              void* d_out, int out_size)
{
    const float* hidden = (const float*)d_in[0];
    const float* rotary = (const float*)d_in[1];
    const int*   cu     = (const int*)d_in[2];
    const float* qkv_w  = (const float*)d_in[3];
    const float* qkv_b  = (const float*)d_in[4];
    const float* proj_w = (const float*)d_in[5];
    const float* proj_b = (const float*)d_in[6];
    float* out = (float*)d_out;
    int ncu = in_sizes[2];

    float *qkv_ptr;
    __half *hidH, *wqH, *wqL, *wpH, *wpL, *atH;
    cudaGetSymbolAddress((void**)&qkv_ptr, g_qkv);
    cudaGetSymbolAddress((void**)&hidH, g_hid_h);
    cudaGetSymbolAddress((void**)&wqH, g_wq_h);
    cudaGetSymbolAddress((void**)&wqL, g_wq_l);
    cudaGetSymbolAddress((void**)&wpH, g_wp_h);
    cudaGetSymbolAddress((void**)&wpL, g_wp_l);
    cudaGetSymbolAddress((void**)&atH, g_at_h);

    cudaFuncSetAttribute(hgemm2_kernel,
                         cudaFuncAttributeMaxDynamicSharedMemorySize, HG_SMEM);

    // 0) Merged decomposition
    {
        int total = HID4 + WQ4 + WP4;
        decomp_all_kernel<<<(total + 255) / 256, 256>>>(
            (const float4*)hidden, (const float4*)qkv_w, (const float4*)proj_w,
            (uint32_t*)hidH, (uint32_t*)wqH, (uint32_t*)wqL,
            (uint32_t*)wpH, (uint32_t*)wpL);
    }

    // 1) QKV GEMM
    hgemm2_kernel<<<dim3(QKV_DIM / 64, SEQ / 128), 256, HG_SMEM>>>(
        hidH, wqH, wqL, qkv_b, qkv_ptr, SEQ, QKV_DIM, DIM);

    // 2) Q/K + V preps (separate, balanced launches)
    qkprep_kernel<<<(SEQ * 40 + 255) / 256, 256>>>(rotary);
    vtprep_kernel<<<dim3(SEQ / 64, HEADS), 256>>>();

    // 3) Flash attention (unmasked fast path)
    {
        cudaFuncSetAttribute(fattn_kernel,
                             cudaFuncAttributeMaxDynamicSharedMemorySize, FA_SMEM);
        fattn_kernel<<<dim3(SEQ / AQ, HEADS), 256, FA_SMEM>>>(cu, ncu);
    }

    // 4) proj GEMM
    hgemm2_kernel<<<dim3(DIM / 64, SEQ / 128), 256, HG_SMEM>>>(
        atH, wpH, wpL, proj_b, out, SEQ, DIM, DIM);
}

// round 15
// speedup vs baseline: 1.2991x; 1.0556x over previous
#include <cuda_runtime.h>
#include <cuda_bf16.h>
#include <cuda_fp16.h>
#include <math.h>
#include <stdint.h>

#define SEQ      2048
#define DIM      1280
#define HEADS    16
#define HEAD_DIM 80
#define QKV_DIM  3840

// ---------------------------------------------------------------------------
// Scratch
// ---------------------------------------------------------------------------
__device__ float g_qkv[SEQ * QKV_DIM];
__device__ __half g_hid_h[SEQ * DIM];
__device__ __half g_wq_h[QKV_DIM * DIM], g_wq_l[QKV_DIM * DIM];
__device__ __half g_wp_h[DIM * DIM],     g_wp_l[DIM * DIM];
__device__ __half g_at_h[SEQ * DIM];
__device__ __nv_bfloat16 g_q_h[HEADS * SEQ * HEAD_DIM], g_q_l[HEADS * SEQ * HEAD_DIM];
__device__ __nv_bfloat16 g_k_h[HEADS * SEQ * HEAD_DIM], g_k_l[HEADS * SEQ * HEAD_DIM];
__device__ __half g_vt_h[HEADS * HEAD_DIM * SEQ];   // single fp16 plane

// ---------------------------------------------------------------------------
// PTX helpers
// ---------------------------------------------------------------------------
#define CP_ASYNC16(dst, src) \
    asm volatile("cp.async.cg.shared.global [%0], [%1], 16;" :: "r"(dst), "l"(src))
#define CP_COMMIT() asm volatile("cp.async.commit_group;")
#define CP_WAIT(n)  asm volatile("cp.async.wait_group %0;" :: "n"(n))

#define LDSM_X4(r0,r1,r2,r3,addr) \
    asm volatile("ldmatrix.sync.aligned.m8n8.x4.shared.b16 {%0,%1,%2,%3}, [%4];" \
        : "=r"(r0),"=r"(r1),"=r"(r2),"=r"(r3) : "r"(addr))
#define LDSM_X2(r0,r1,addr) \
    asm volatile("ldmatrix.sync.aligned.m8n8.x2.shared.b16 {%0,%1}, [%2];" \
        : "=r"(r0),"=r"(r1) : "r"(addr))

#define MMA16816(c0,c1,c2,c3,a0,a1,a2,a3,b0,b1) \
    asm volatile("mma.sync.aligned.m16n8k16.row.col.f32.bf16.bf16.f32 " \
        "{%0,%1,%2,%3}, {%4,%5,%6,%7}, {%8,%9}, {%0,%1,%2,%3};" \
        : "+f"(c0),"+f"(c1),"+f"(c2),"+f"(c3) \
        : "r"(a0),"r"(a1),"r"(a2),"r"(a3),"r"(b0),"r"(b1))

#define MMAH16816(c0,c1,c2,c3,a0,a1,a2,a3,b0,b1) \
    asm volatile("mma.sync.aligned.m16n8k16.row.col.f32.f16.f16.f32 " \
        "{%0,%1,%2,%3}, {%4,%5,%6,%7}, {%8,%9}, {%0,%1,%2,%3};" \
        : "+f"(c0),"+f"(c1),"+f"(c2),"+f"(c3) \
        : "r"(a0),"r"(a1),"r"(a2),"r"(a3),"r"(b0),"r"(b1))

__device__ __forceinline__ uint32_t smem_u32(const void* p) {
    return (uint32_t)__cvta_generic_to_shared(p);
}
__device__ __forceinline__ uint32_t pack_bf2(float a, float b) {
    __nv_bfloat162 v = __float22bfloat162_rn(make_float2(a, b));
    return *(uint32_t*)&v;
}
__device__ __forceinline__ uint32_t pack_h2(float a, float b) {
    __half2 v = __floats2half2_rn(a, b);
    return *(uint32_t*)&v;
}

// ---------------------------------------------------------------------------
// fp16 2-term HGEMM (round-10, at HMMA roofline — unchanged)
// ---------------------------------------------------------------------------
#define KBLK 32
#define KPAD 40
#define APLANE_B (128 * KPAD * 2)
#define BPLANE_B (64 * KPAD * 2)
#define STAGE_B (APLANE_B + 2 * BPLANE_B)
#define HG_SMEM (2 * STAGE_B)

__global__ void __launch_bounds__(256, 3) hgemm2_kernel(
    const __half* __restrict__ Ah_,
    const __half* __restrict__ Bh_, const __half* __restrict__ Bl_,
    const float* __restrict__ bias, float* __restrict__ C,
    int M, int N, int K)
{
    extern __shared__ char smraw[];
    const uint32_t sb = smem_u32(smraw);

    const int tid = threadIdx.x;
    const int ln  = tid & 31;
    const int wid = tid >> 5;
    const int wm  = wid >> 1;
    const int wn  = wid & 1;
    const int m0  = blockIdx.y * 128;
    const int n0  = blockIdx.x * 64;

    const __half* gA = Ah_ + (size_t)m0 * K;
    const __half* gB[2] = { Bh_ + (size_t)n0 * K, Bl_ + (size_t)n0 * K };

    const int arow0 = tid >> 2;
    const int arow1 = (tid + 256) >> 2;
    const int brow  = tid >> 2;
    const int kc16  = (tid & 3) * 8;

    auto load_stage = [&](int kt, int s) {
        const uint32_t stb = sb + s * STAGE_B;
        CP_ASYNC16(stb + (uint32_t)(arow0 * KPAD + kc16) * 2,
                   gA + (size_t)arow0 * K + kt + kc16);
        CP_ASYNC16(stb + (uint32_t)(arow1 * KPAD + kc16) * 2,
                   gA + (size_t)arow1 * K + kt + kc16);
        #pragma unroll
        for (int p = 0; p < 2; p++) {
            const uint32_t pb = stb + APLANE_B + p * BPLANE_B;
            CP_ASYNC16(pb + (uint32_t)(brow * KPAD + kc16) * 2,
                       gB[p] + (size_t)brow * K + kt + kc16);
        }
        CP_COMMIT();
    };

    float acc[2][4][4];
    #pragma unroll
    for (int mi = 0; mi < 2; mi++)
        #pragma unroll
        for (int ni = 0; ni < 4; ni++)
            #pragma unroll
            for (int c = 0; c < 4; c++) acc[mi][ni][c] = 0.f;

    load_stage(0, 0);
    CP_WAIT(0);
    __syncthreads();

    const int a_row = (ln & 15);
    const int a_kof = (ln < 16) ? 0 : 8;
    const int b_row = (ln & 7);
    const int b_kof = (ln & 8);

    int buf = 0;
    for (int kt = 0; kt < K; kt += KBLK) {
        const bool hasNext = (kt + KBLK) < K;
        if (hasNext) load_stage(kt + KBLK, buf ^ 1);

        const uint32_t stb = sb + buf * STAGE_B;
        const uint32_t pAh = stb;
        const uint32_t pBh = stb + APLANE_B;
        const uint32_t pBl = stb + APLANE_B + BPLANE_B;

        #pragma unroll
        for (int ks = 0; ks < 2; ks++) {
            const int k0 = ks * 16;
            uint32_t ah[2][4];
            #pragma unroll
            for (int mi = 0; mi < 2; mi++) {
                uint32_t off = (uint32_t)((wm * 32 + mi * 16 + a_row) * KPAD
                                          + k0 + a_kof) * 2;
                LDSM_X4(ah[mi][0], ah[mi][1], ah[mi][2], ah[mi][3], pAh + off);
            }
            uint32_t bh[4][2], bl[4][2];
            #pragma unroll
            for (int ni = 0; ni < 4; ni++) {
                uint32_t off = (uint32_t)((wn * 32 + ni * 8 + b_row) * KPAD
                                          + k0 + b_kof) * 2;
                LDSM_X2(bh[ni][0], bh[ni][1], pBh + off);
                LDSM_X2(bl[ni][0], bl[ni][1], pBl + off);
            }
            #pragma unroll
            for (int ni = 0; ni < 4; ni++)
                #pragma unroll
                for (int mi = 0; mi < 2; mi++)
                    MMAH16816(acc[mi][ni][0], acc[mi][ni][1],
                              acc[mi][ni][2], acc[mi][ni][3],
                              ah[mi][0], ah[mi][1], ah[mi][2], ah[mi][3],
                              bh[ni][0], bh[ni][1]);
            #pragma unroll
            for (int ni = 0; ni < 4; ni++)
                #pragma unroll
                for (int mi = 0; mi < 2; mi++)
                    MMAH16816(acc[mi][ni][0], acc[mi][ni][1],
                              acc[mi][ni][2], acc[mi][ni][3],
                              ah[mi][0], ah[mi][1], ah[mi][2], ah[mi][3],
                              bl[ni][0], bl[ni][1]);
        }

        if (hasNext) {
            CP_WAIT(0);
            __syncthreads();
            buf ^= 1;
        }
    }

    const int crow = ln >> 2;
    const int ccol = (ln & 3) * 2;
    #pragma unroll
    for (int mi = 0; mi < 2; mi++) {
        #pragma unroll
        for (int ni = 0; ni < 4; ni++) {
            int col = n0 + wn * 32 + ni * 8 + ccol;
            float b0 = bias[col], b1 = bias[col + 1];
            int r0 = m0 + wm * 32 + mi * 16 + crow;
            float2 v0 = make_float2(acc[mi][ni][0] + b0, acc[mi][ni][1] + b1);
            float2 v1 = make_float2(acc[mi][ni][2] + b0, acc[mi][ni][3] + b1);
            *(float2*)(C + (size_t)r0 * N + col)       = v0;
            *(float2*)(C + (size_t)(r0 + 8) * N + col) = v1;
        }
    }
}

// ---------------------------------------------------------------------------
// Merged decompose: hidden (hi only) + qkv_w (hi/lo) + proj_w (hi/lo)
// ---------------------------------------------------------------------------
#define HID4 (SEQ * DIM / 4)
#define WQ4  (QKV_DIM * DIM / 4)
#define WP4  (DIM * DIM / 4)

__global__ void __launch_bounds__(256) decomp_all_kernel(
    const float4* __restrict__ hid, const float4* __restrict__ wq,
    const float4* __restrict__ wp,
    uint32_t* __restrict__ hidH,
    uint32_t* __restrict__ wqH, uint32_t* __restrict__ wqL,
    uint32_t* __restrict__ wpH, uint32_t* __restrict__ wpL)
{
    int idx = blockIdx.x * blockDim.x + threadIdx.x;
    if (idx < HID4) {
        float4 v = hid[idx];
        hidH[idx * 2]     = pack_h2(v.x, v.y);
        hidH[idx * 2 + 1] = pack_h2(v.z, v.w);
        return;
    }
    const float4* src;
    uint32_t *dh, *dl;
    int j;
    if (idx < HID4 + WQ4) {
        j = idx - HID4;  src = wq; dh = wqH; dl = wqL;
    } else if (idx < HID4 + WQ4 + WP4) {
        j = idx - HID4 - WQ4;  src = wp; dh = wpH; dl = wpL;
    } else return;

    float4 v = src[j];
    __half h0 = __float2half_rn(v.x);
    __half h1 = __float2half_rn(v.y);
    __half h2 = __float2half_rn(v.z);
    __half h3 = __float2half_rn(v.w);
    dh[j * 2]     = pack_h2(v.x, v.y);
    dh[j * 2 + 1] = pack_h2(v.z, v.w);
    dl[j * 2]     = pack_h2(v.x - __half2float(h0), v.y - __half2float(h1));
    dl[j * 2 + 1] = pack_h2(v.z - __half2float(h2), v.w - __half2float(h3));
}

// ---------------------------------------------------------------------------
// Balanced merged prep: blocks [0,512) = V transpose (same work as vtprep),
// blocks [512, 832) = rope+scale Q/K decomp (same work as qkprep).
// ---------------------------------------------------------------------------
__global__ void __launch_bounds__(256) prep_kernel(const float* __restrict__ rot)
{
    const int tid = threadIdx.x;
    const int bid = blockIdx.x;

    if (bid < 512) {
        // ---- V transpose + fp16 plane: h = bid & 15, s0 = (bid >> 4) * 64 ----
        __shared__ float T[HEAD_DIM][65];
        const int h  = bid & 15;
        const int s0 = (bid >> 4) * 64;
        #pragma unroll
        for (int i = 0; i < 20; i++) {
            int idx = tid + i * 256;
            int r = idx / HEAD_DIM, d = idx % HEAD_DIM;
            T[d][r] = g_qkv[(size_t)(s0 + r) * QKV_DIM + 2 * DIM + h * HEAD_DIM + d];
        }
        __syncthreads();
        #pragma unroll
        for (int i = 0; i < 20; i++) {
            int idx = tid + i * 256;
            int d = idx / 64, r = idx % 64;
            size_t o = ((size_t)h * HEAD_DIM + d) * SEQ + s0 + r;
            g_vt_h[o] = __float2half_rn(T[d][r]);
        }
    } else {
        // ---- Q/K rope + scale + bf16 hi/lo; sincos reused across heads ----
        int t = (bid - 512) * 256 + tid;
        if (t >= SEQ * 40) return;
        int d2 = t % 40;
        int s  = t / 40;

        float f = rot[s * 40 + d2];
        float si, co;
        sincosf(f, &si, &co);
        const float scale = rsqrtf((float)HEAD_DIM);

        #pragma unroll 4
        for (int h = 0; h < HEADS; h++) {
            size_t qb = (size_t)s * QKV_DIM + h * HEAD_DIM;
            float q1 = g_qkv[qb + d2],        q2 = g_qkv[qb + 40 + d2];
            float k1 = g_qkv[qb + DIM + d2],  k2 = g_qkv[qb + DIM + 40 + d2];

            float qr1 = (q1 * co - q2 * si) * scale;
            float qr2 = (q2 * co + q1 * si) * scale;
            float kr1 = k1 * co - k2 * si;
            float kr2 = k2 * co + k1 * si;

            size_t ob = ((size_t)h * SEQ + s) * HEAD_DIM;
            __nv_bfloat16 hq1 = __float2bfloat16(qr1);
            __nv_bfloat16 hq2 = __float2bfloat16(qr2);
            __nv_bfloat16 hk1 = __float2bfloat16(kr1);
            __nv_bfloat16 hk2 = __float2bfloat16(kr2);
            g_q_h[ob + d2]      = hq1;
            g_q_h[ob + 40 + d2] = hq2;
            g_q_l[ob + d2]      = __float2bfloat16(qr1 - __bfloat162float(hq1));
            g_q_l[ob + 40 + d2] = __float2bfloat16(qr2 - __bfloat162float(hq2));
            g_k_h[ob + d2]      = hk1;
            g_k_h[ob + 40 + d2] = hk2;
            g_k_l[ob + d2]      = __float2bfloat16(kr1 - __bfloat162float(hk1));
            g_k_l[ob + 40 + d2] = __float2bfloat16(kr2 - __bfloat162float(hk2));
        }
    }
}

// ---------------------------------------------------------------------------
// Tensor-core flash attention: AK=32, 2 CTAs/SM, nomask fast path,
// QK bf16 3-term, PV fp16 2-term (V single plane).
// ---------------------------------------------------------------------------
#define AQ    128
#define AK    32
#define QSTR  88
#define VSTR  40
#define QPL   (AQ * QSTR * 2)        // 22528
#define KPL   (AK * QSTR * 2)        // 5632
#define VPL   (HEAD_DIM * VSTR * 2)  // 6400 (single fp16 plane)
#define KSTG  (2 * KPL)
#define FA_SMEM (2*QPL + 2*KSTG + 2*VPL + (AQ + 2*AK + 8) * 4)

__global__ void __launch_bounds__(256, 2) fattn_kernel(const int* __restrict__ cu, int ncu)
{
    extern __shared__ char smraw[];
    char* Qb  = smraw;
    char* Kb  = Qb + 2 * QPL;
    char* Vb  = Kb + 2 * KSTG;
    int* segq  = (int*)(Vb + 2 * VPL);
    int* segk  = segq + AQ;
    int* range = segk + 2 * AK;        // [0]=lo [1]=hi [2]=nomask

    const int tid = threadIdx.x;
    const int w   = tid >> 5;
    const int ln  = tid & 31;
    const int head  = blockIdx.y;
    const int qbase = blockIdx.x * AQ;

    const __nv_bfloat16* gq[2] = { g_q_h, g_q_l };
    const __nv_bfloat16* gk[2] = { g_k_h, g_k_l };

    {
        const uint32_t qs = smem_u32(Qb);
        #pragma unroll
        for (int i = 0; i < 10; i++) {
            int idx = tid + i * 256;
            int pl = idx / 1280, rem = idx % 1280;
            int r = rem / 10, c = rem % 10;
            CP_ASYNC16(qs + pl * QPL + (uint32_t)(r * QSTR + c * 8) * 2,
                       gq[pl] + ((size_t)head * SEQ + qbase + r) * HEAD_DIM + c * 8);
        }
        CP_COMMIT();
    }
    if (tid < AQ) {
        int i = qbase + tid;
        int s = 0;
        for (int j = 1; j < ncu; j++) s += (cu[j] <= i);
        segq[tid] = s;
    }
    __syncthreads();
    if (tid == 0) {
        int smin = segq[0], smax = segq[AQ - 1];
        for (int r = 1; r < AQ; r++) { smin = min(smin, segq[r]); smax = max(smax, segq[r]); }
        int lo = cu[smin], hi = cu[smax + 1];
        range[0] = lo;
        range[1] = hi;
        range[2] = (smin == smax) && (((hi - lo) % AK) == 0);
    }
    __syncthreads();
    const int lo = range[0], hi_ = range[1];
    const bool nomask = (range[2] != 0);

    // K/V loader: K = 640 chunks (2 planes), V = 320 chunks (1 plane) -> 960
    auto load_kv = [&](int kt, int st) {
        const uint32_t ks = smem_u32(Kb) + st * KSTG;
        const uint32_t vs = smem_u32(Vb) + st * VPL;
        #pragma unroll
        for (int i = 0; i < 4; i++) {
            int idx = tid + i * 256;
            if (idx < 640) {
                int pl = idx / 320, rem = idx % 320;
                int r = rem / 10, c = rem % 10;
                int row = min(kt + r, SEQ - 1);
                CP_ASYNC16(ks + pl * KPL + (uint32_t)(r * QSTR + c * 8) * 2,
                           gk[pl] + ((size_t)head * SEQ + row) * HEAD_DIM + c * 8);
            } else if (idx < 960) {
                int j = idx - 640;
                int d = j / 4, c = j % 4;
                int col = min(kt + c * 8, SEQ - 8);
                CP_ASYNC16(vs + (uint32_t)(d * VSTR + c * 8) * 2,
                           g_vt_h + ((size_t)head * HEAD_DIM + d) * SEQ + col);
            }
        }
        CP_COMMIT();
    };

    const int qr = ln >> 2;
    const int kq = (ln & 3) * 2;
    const int row0 = w * 16 + qr;
    const int row1 = row0 + 8;
    const int sq0 = segq[row0], sq1 = segq[row1];

    float m0 = -1e30f, m1 = -1e30f, l0 = 0.f, l1 = 0.f;
    float acc[10][4];
    #pragma unroll
    for (int n = 0; n < 10; n++)
        #pragma unroll
        for (int c = 0; c < 4; c++) acc[n][c] = 0.f;

    const int a_row = (ln & 15);
    const int a_kof = (ln < 16) ? 0 : 8;
    const int b_row = (ln & 7);
    const int b_kof = (ln & 8);

    load_kv(lo, 0);
    CP_WAIT(0);
    __syncthreads();

    int st = 0;
    for (int kt = lo; kt < hi_; kt += AK) {
        const bool hasNext = (kt + AK) < hi_;
        if (hasNext) load_kv(kt + AK, st ^ 1);

        if (!nomask && tid < AK) {
            int key = kt + tid;
            int s = -1;
            if (key < hi_) {
                s = 0;
                for (int j = 1; j < ncu; j++) s += (cu[j] <= key);
            }
            segk[st * AK + tid] = s;
        }
        if (hasNext) { CP_WAIT(1); } else { CP_WAIT(0); }
        __syncthreads();

        const uint32_t pQh = smem_u32(Qb);
        const uint32_t pQl = pQh + QPL;
        const uint32_t pKh = smem_u32(Kb) + st * KSTG;
        const uint32_t pKl = pKh + KPL;
        const uint32_t pVh = smem_u32(Vb) + st * VPL;
        const int* sk = segk + st * AK;

        // ---- S = Q @ K^T, bf16 3-term ----
        float S[4][4];
        #pragma unroll
        for (int j = 0; j < 4; j++)
            #pragma unroll
            for (int c = 0; c < 4; c++) S[j][c] = 0.f;

        #pragma unroll
        for (int kc = 0; kc < 5; kc++) {
            uint32_t ah[4], al[4];
            uint32_t qoff = (uint32_t)((w * 16 + a_row) * QSTR + kc * 16 + a_kof) * 2;
            LDSM_X4(ah[0], ah[1], ah[2], ah[3], pQh + qoff);
            LDSM_X4(al[0], al[1], al[2], al[3], pQl + qoff);
            uint32_t bh[4][2], bl[4][2];
            #pragma unroll
            for (int q = 0; q < 4; q++) {
                uint32_t koff = (uint32_t)((q * 8 + b_row) * QSTR
                                           + kc * 16 + b_kof) * 2;
                LDSM_X2(bh[q][0], bh[q][1], pKh + koff);
                LDSM_X2(bl[q][0], bl[q][1], pKl + koff);
            }
            #pragma unroll
            for (int q = 0; q < 4; q++)
                MMA16816(S[q][0], S[q][1], S[q][2], S[q][3],
                         ah[0], ah[1], ah[2], ah[3], bh[q][0], bh[q][1]);
            #pragma unroll
            for (int q = 0; q < 4; q++)
                MMA16816(S[q][0], S[q][1], S[q][2], S[q][3],
                         ah[0], ah[1], ah[2], ah[3], bl[q][0], bl[q][1]);
            #pragma unroll
            for (int q = 0; q < 4; q++)
                MMA16816(S[q][0], S[q][1], S[q][2], S[q][3],
                         al[0], al[1], al[2], al[3], bh[q][0], bh[q][1]);
        }

        // ---- online softmax ----
        float mt0 = -1e30f, mt1 = -1e30f;
        float rs0 = 0.f, rs1 = 0.f;
        if (nomask) {
            #pragma unroll
            for (int j = 0; j < 4; j++) {
                mt0 = fmaxf(mt0, fmaxf(S[j][0], S[j][1]));
                mt1 = fmaxf(mt1, fmaxf(S[j][2], S[j][3]));
            }
            #pragma unroll
            for (int msk = 1; msk <= 2; msk <<= 1) {
                mt0 = fmaxf(mt0, __shfl_xor_sync(0xffffffffu, mt0, msk));
                mt1 = fmaxf(mt1, __shfl_xor_sync(0xffffffffu, mt1, msk));
            }
            float mn0 = fmaxf(m0, mt0), mn1 = fmaxf(m1, mt1);
            float alpha0 = __expf(m0 - mn0), alpha1 = __expf(m1 - mn1);
            #pragma unroll
            for (int j = 0; j < 4; j++) {
                float p0 = __expf(S[j][0] - mn0);
                float p1 = __expf(S[j][1] - mn0);
                float p2 = __expf(S[j][2] - mn1);
                float p3 = __expf(S[j][3] - mn1);
                S[j][0] = p0; S[j][1] = p1; S[j][2] = p2; S[j][3] = p3;
                rs0 += p0 + p1;
                rs1 += p2 + p3;
            }
            #pragma unroll
            for (int msk = 1; msk <= 2; msk <<= 1) {
                rs0 += __shfl_xor_sync(0xffffffffu, rs0, msk);
                rs1 += __shfl_xor_sync(0xffffffffu, rs1, msk);
            }
            l0 = l0 * alpha0 + rs0;
            l1 = l1 * alpha1 + rs1;
            m0 = mn0; m1 = mn1;
            #pragma unroll
            for (int n = 0; n < 10; n++) {
                acc[n][0] *= alpha0; acc[n][1] *= alpha0;
                acc[n][2] *= alpha1; acc[n][3] *= alpha1;
            }
        } else {
            #pragma unroll
            for (int j = 0; j < 4; j++) {
                int k0 = j * 8 + kq;
                int sk0 = sk[k0], sk1 = sk[k0 + 1];
                mt0 = fmaxf(mt0, (sk0 == sq0) ? S[j][0] : -1e30f);
                mt0 = fmaxf(mt0, (sk1 == sq0) ? S[j][1] : -1e30f);
                mt1 = fmaxf(mt1, (sk0 == sq1) ? S[j][2] : -1e30f);
                mt1 = fmaxf(mt1, (sk1 == sq1) ? S[j][3] : -1e30f);
            }
            #pragma unroll
            for (int msk = 1; msk <= 2; msk <<= 1) {
                mt0 = fmaxf(mt0, __shfl_xor_sync(0xffffffffu, mt0, msk));
                mt1 = fmaxf(mt1, __shfl_xor_sync(0xffffffffu, mt1, msk));
            }
            float mn0 = fmaxf(m0, mt0), mn1 = fmaxf(m1, mt1);
            float alpha0 = __expf(m0 - mn0), alpha1 = __expf(m1 - mn1);
            #pragma unroll
            for (int j = 0; j < 4; j++) {
                int k0 = j * 8 + kq;
                int sk0 = sk[k0], sk1 = sk[k0 + 1];
                float p0 = (sk0 == sq0) ? __expf(S[j][0] - mn0) : 0.f;
                float p1 = (sk1 == sq0) ? __expf(S[j][1] - mn0) : 0.f;
                float p2 = (sk0 == sq1) ? __expf(S[j][2] - mn1) : 0.f;
                float p3 = (sk1 == sq1) ? __expf(S[j][3] - mn1) : 0.f;
                S[j][0] = p0; S[j][1] = p1; S[j][2] = p2; S[j][3] = p3;
                rs0 += p0 + p1;
                rs1 += p2 + p3;
            }
            #pragma unroll
            for (int msk = 1; msk <= 2; msk <<= 1) {
                rs0 += __shfl_xor_sync(0xffffffffu, rs0, msk);
                rs1 += __shfl_xor_sync(0xffffffffu, rs1, msk);
            }
            l0 = l0 * alpha0 + rs0;
            l1 = l1 * alpha1 + rs1;
            m0 = mn0; m1 = mn1;
            #pragma unroll
            for (int n = 0; n < 10; n++) {
                acc[n][0] *= alpha0; acc[n][1] *= alpha0;
                acc[n][2] *= alpha1; acc[n][3] *= alpha1;
            }
        }

        // ---- O += P @ V, fp16 2-term (P hi/lo, V single plane) ----
        #pragma unroll
        for (int jc = 0; jc < 2; jc++) {
            float h00 = __half2float(__float2half_rn(S[2*jc][0]));
            float h01 = __half2float(__float2half_rn(S[2*jc][1]));
            float h02 = __half2float(__float2half_rn(S[2*jc][2]));
            float h03 = __half2float(__float2half_rn(S[2*jc][3]));
            float h10 = __half2float(__float2half_rn(S[2*jc+1][0]));
            float h11 = __half2float(__float2half_rn(S[2*jc+1][1]));
            float h12 = __half2float(__float2half_rn(S[2*jc+1][2]));
            float h13 = __half2float(__float2half_rn(S[2*jc+1][3]));
            uint32_t aPh[4], aPl[4];
            aPh[0] = pack_h2(h00, h01);
            aPh[1] = pack_h2(h02, h03);
            aPh[2] = pack_h2(h10, h11);
            aPh[3] = pack_h2(h12, h13);
            aPl[0] = pack_h2(S[2*jc][0] - h00, S[2*jc][1] - h01);
            aPl[1] = pack_h2(S[2*jc][2] - h02, S[2*jc][3] - h03);
            aPl[2] = pack_h2(S[2*jc+1][0] - h10, S[2*jc+1][1] - h11);
            aPl[3] = pack_h2(S[2*jc+1][2] - h12, S[2*jc+1][3] - h13);

            #pragma unroll
            for (int ng = 0; ng < 3; ng++) {
                const int gs = ng * 4;
                const int gn = (ng == 2) ? 2 : 4;
                uint32_t bh[4][2];
                #pragma unroll
                for (int q = 0; q < 4; q++) {
                    if (q < gn) {
                        uint32_t voff = (uint32_t)(((gs + q) * 8 + b_row) * VSTR
                                                   + jc * 16 + b_kof) * 2;
                        LDSM_X2(bh[q][0], bh[q][1], pVh + voff);
                    }
                }
                #pragma unroll
                for (int q = 0; q < 4; q++)
                    if (q < gn)
                        MMAH16816(acc[gs+q][0], acc[gs+q][1], acc[gs+q][2], acc[gs+q][3],
                                  aPh[0], aPh[1], aPh[2], aPh[3], bh[q][0], bh[q][1]);
                #pragma unroll
                for (int q = 0; q < 4; q++)
                    if (q < gn)
                        MMAH16816(acc[gs+q][0], acc[gs+q][1], acc[gs+q][2], acc[gs+q][3],
                                  aPl[0], aPl[1], aPl[2], aPl[3], bh[q][0], bh[q][1]);
            }
        }

        __syncthreads();
        st ^= 1;
    }

    float il0 = (l0 > 0.f) ? (1.f / l0) : 0.f;
    float il1 = (l1 > 0.f) ? (1.f / l1) : 0.f;
    #pragma unroll
    for (int n = 0; n < 10; n++) {
        int d = n * 8 + kq;
        size_t o0 = (size_t)(qbase + row0) * DIM + head * HEAD_DIM + d;
        size_t o1 = (size_t)(qbase + row1) * DIM + head * HEAD_DIM + d;
        *(uint32_t*)&g_at_h[o0] = pack_h2(acc[n][0] * il0, acc[n][1] * il0);
        *(uint32_t*)&g_at_h[o1] = pack_h2(acc[n][2] * il1, acc[n][3] * il1);
    }
}

// ---------------------------------------------------------------------------
extern "C" void kernel_launch(void* const* d_in, const int* in_sizes, int n_in,
                              void* d_out, int out_size)
{
    const float* hidden = (const float*)d_in[0];
    const float* rotary = (const float*)d_in[1];
    const int*   cu     = (const int*)d_in[2];
    const float* qkv_w  = (const float*)d_in[3];
    const float* qkv_b  = (const float*)d_in[4];
    const float* proj_w = (const float*)d_in[5];
    const float* proj_b = (const float*)d_in[6];
    float* out = (float*)d_out;
    int ncu = in_sizes[2];

    float *qkv_ptr;
    __half *hidH, *wqH, *wqL, *wpH, *wpL, *atH;
    cudaGetSymbolAddress((void**)&qkv_ptr, g_qkv);
    cudaGetSymbolAddress((void**)&hidH, g_hid_h);
    cudaGetSymbolAddress((void**)&wqH, g_wq_h);
    cudaGetSymbolAddress((void**)&wqL, g_wq_l);
    cudaGetSymbolAddress((void**)&wpH, g_wp_h);
    cudaGetSymbolAddress((void**)&wpL, g_wp_l);
    cudaGetSymbolAddress((void**)&atH, g_at_h);

    cudaFuncSetAttribute(hgemm2_kernel,
                         cudaFuncAttributeMaxDynamicSharedMemorySize, HG_SMEM);

    // 0) Merged decomposition
    {
        int total = HID4 + WQ4 + WP4;
        decomp_all_kernel<<<(total + 255) / 256, 256>>>(
            (const float4*)hidden, (const float4*)qkv_w, (const float4*)proj_w,
            (uint32_t*)hidH, (uint32_t*)wqH, (uint32_t*)wqL,
            (uint32_t*)wpH, (uint32_t*)wpL);
    }

    // 1) QKV GEMM
    hgemm2_kernel<<<dim3(QKV_DIM / 64, SEQ / 128), 256, HG_SMEM>>>(
        hidH, wqH, wqL, qkv_b, qkv_ptr, SEQ, QKV_DIM, DIM);

    // 2) Balanced merged prep (512 V-blocks + 320 QK-blocks)
    prep_kernel<<<832, 256>>>(rotary);

    // 3) Flash attention
    {
        cudaFuncSetAttribute(fattn_kernel,
                             cudaFuncAttributeMaxDynamicSharedMemorySize, FA_SMEM);
        fattn_kernel<<<dim3(SEQ / AQ, HEADS), 256, FA_SMEM>>>(cu, ncu);
    }

    // 4) proj GEMM
    hgemm2_kernel<<<dim3(DIM / 64, SEQ / 128), 256, HG_SMEM>>>(
        atH, wpH, wpL, proj_b, out, SEQ, DIM, DIM);
}

// round 16
// speedup vs baseline: 1.3765x; 1.0595x over previous
#include <cuda_runtime.h>
#include <cuda_bf16.h>
#include <cuda_fp16.h>
#include <math.h>
#include <stdint.h>

#define SEQ      2048
#define DIM      1280
#define HEADS    16
#define HEAD_DIM 80
#define QKV_DIM  3840

// ---------------------------------------------------------------------------
// Scratch
// ---------------------------------------------------------------------------
__device__ float g_qkv[SEQ * QKV_DIM];
__device__ __half g_hid_h[SEQ * DIM];
__device__ __half g_wq_h[QKV_DIM * DIM], g_wq_l[QKV_DIM * DIM];
__device__ __half g_wp_h[DIM * DIM],     g_wp_l[DIM * DIM];
__device__ __half g_at_h[SEQ * DIM];
__device__ __half g_q_h[HEADS * SEQ * HEAD_DIM];    // single fp16 plane (scaled)
__device__ __half g_k_h[HEADS * SEQ * HEAD_DIM];    // single fp16 plane
__device__ __half g_vt_h[HEADS * HEAD_DIM * SEQ];   // single fp16 plane, [h][d][s]

// ---------------------------------------------------------------------------
// PTX helpers
// ---------------------------------------------------------------------------
#define CP_ASYNC16(dst, src) \
    asm volatile("cp.async.cg.shared.global [%0], [%1], 16;" :: "r"(dst), "l"(src))
#define CP_COMMIT() asm volatile("cp.async.commit_group;")
#define CP_WAIT(n)  asm volatile("cp.async.wait_group %0;" :: "n"(n))

#define LDSM_X4(r0,r1,r2,r3,addr) \
    asm volatile("ldmatrix.sync.aligned.m8n8.x4.shared.b16 {%0,%1,%2,%3}, [%4];" \
        : "=r"(r0),"=r"(r1),"=r"(r2),"=r"(r3) : "r"(addr))
#define LDSM_X2(r0,r1,addr) \
    asm volatile("ldmatrix.sync.aligned.m8n8.x2.shared.b16 {%0,%1}, [%2];" \
        : "=r"(r0),"=r"(r1) : "r"(addr))

#define MMAH16816(c0,c1,c2,c3,a0,a1,a2,a3,b0,b1) \
    asm volatile("mma.sync.aligned.m16n8k16.row.col.f32.f16.f16.f32 " \
        "{%0,%1,%2,%3}, {%4,%5,%6,%7}, {%8,%9}, {%0,%1,%2,%3};" \
        : "+f"(c0),"+f"(c1),"+f"(c2),"+f"(c3) \
        : "r"(a0),"r"(a1),"r"(a2),"r"(a3),"r"(b0),"r"(b1))

__device__ __forceinline__ uint32_t smem_u32(const void* p) {
    return (uint32_t)__cvta_generic_to_shared(p);
}
__device__ __forceinline__ uint32_t pack_h2(float a, float b) {
    __half2 v = __floats2half2_rn(a, b);
    return *(uint32_t*)&v;
}

// ---------------------------------------------------------------------------
// fp16 2-term HGEMM (round-10, at HMMA roofline — unchanged)
// ---------------------------------------------------------------------------
#define KBLK 32
#define KPAD 40
#define APLANE_B (128 * KPAD * 2)
#define BPLANE_B (64 * KPAD * 2)
#define STAGE_B (APLANE_B + 2 * BPLANE_B)
#define HG_SMEM (2 * STAGE_B)

__global__ void __launch_bounds__(256, 3) hgemm2_kernel(
    const __half* __restrict__ Ah_,
    const __half* __restrict__ Bh_, const __half* __restrict__ Bl_,
    const float* __restrict__ bias, float* __restrict__ C,
    int M, int N, int K)
{
    extern __shared__ char smraw[];
    const uint32_t sb = smem_u32(smraw);

    const int tid = threadIdx.x;
    const int ln  = tid & 31;
    const int wid = tid >> 5;
    const int wm  = wid >> 1;
    const int wn  = wid & 1;
    const int m0  = blockIdx.y * 128;
    const int n0  = blockIdx.x * 64;

    const __half* gA = Ah_ + (size_t)m0 * K;
    const __half* gB[2] = { Bh_ + (size_t)n0 * K, Bl_ + (size_t)n0 * K };

    const int arow0 = tid >> 2;
    const int arow1 = (tid + 256) >> 2;
    const int brow  = tid >> 2;
    const int kc16  = (tid & 3) * 8;

    auto load_stage = [&](int kt, int s) {
        const uint32_t stb = sb + s * STAGE_B;
        CP_ASYNC16(stb + (uint32_t)(arow0 * KPAD + kc16) * 2,
                   gA + (size_t)arow0 * K + kt + kc16);
        CP_ASYNC16(stb + (uint32_t)(arow1 * KPAD + kc16) * 2,
                   gA + (size_t)arow1 * K + kt + kc16);
        #pragma unroll
        for (int p = 0; p < 2; p++) {
            const uint32_t pb = stb + APLANE_B + p * BPLANE_B;
            CP_ASYNC16(pb + (uint32_t)(brow * KPAD + kc16) * 2,
                       gB[p] + (size_t)brow * K + kt + kc16);
        }
        CP_COMMIT();
    };

    float acc[2][4][4];
    #pragma unroll
    for (int mi = 0; mi < 2; mi++)
        #pragma unroll
        for (int ni = 0; ni < 4; ni++)
            #pragma unroll
            for (int c = 0; c < 4; c++) acc[mi][ni][c] = 0.f;

    load_stage(0, 0);
    CP_WAIT(0);
    __syncthreads();

    const int a_row = (ln & 15);
    const int a_kof = (ln < 16) ? 0 : 8;
    const int b_row = (ln & 7);
    const int b_kof = (ln & 8);

    int buf = 0;
    for (int kt = 0; kt < K; kt += KBLK) {
        const bool hasNext = (kt + KBLK) < K;
        if (hasNext) load_stage(kt + KBLK, buf ^ 1);

        const uint32_t stb = sb + buf * STAGE_B;
        const uint32_t pAh = stb;
        const uint32_t pBh = stb + APLANE_B;
        const uint32_t pBl = stb + APLANE_B + BPLANE_B;

        #pragma unroll
        for (int ks = 0; ks < 2; ks++) {
            const int k0 = ks * 16;
            uint32_t ah[2][4];
            #pragma unroll
            for (int mi = 0; mi < 2; mi++) {
                uint32_t off = (uint32_t)((wm * 32 + mi * 16 + a_row) * KPAD
                                          + k0 + a_kof) * 2;
                LDSM_X4(ah[mi][0], ah[mi][1], ah[mi][2], ah[mi][3], pAh + off);
            }
            uint32_t bh[4][2], bl[4][2];
            #pragma unroll
            for (int ni = 0; ni < 4; ni++) {
                uint32_t off = (uint32_t)((wn * 32 + ni * 8 + b_row) * KPAD
                                          + k0 + b_kof) * 2;
                LDSM_X2(bh[ni][0], bh[ni][1], pBh + off);
                LDSM_X2(bl[ni][0], bl[ni][1], pBl + off);
            }
            #pragma unroll
            for (int ni = 0; ni < 4; ni++)
                #pragma unroll
                for (int mi = 0; mi < 2; mi++)
                    MMAH16816(acc[mi][ni][0], acc[mi][ni][1],
                              acc[mi][ni][2], acc[mi][ni][3],
                              ah[mi][0], ah[mi][1], ah[mi][2], ah[mi][3],
                              bh[ni][0], bh[ni][1]);
            #pragma unroll
            for (int ni = 0; ni < 4; ni++)
                #pragma unroll
                for (int mi = 0; mi < 2; mi++)
                    MMAH16816(acc[mi][ni][0], acc[mi][ni][1],
                              acc[mi][ni][2], acc[mi][ni][3],
                              ah[mi][0], ah[mi][1], ah[mi][2], ah[mi][3],
                              bl[ni][0], bl[ni][1]);
        }

        if (hasNext) {
            CP_WAIT(0);
            __syncthreads();
            buf ^= 1;
        }
    }

    const int crow = ln >> 2;
    const int ccol = (ln & 3) * 2;
    #pragma unroll
    for (int mi = 0; mi < 2; mi++) {
        #pragma unroll
        for (int ni = 0; ni < 4; ni++) {
            int col = n0 + wn * 32 + ni * 8 + ccol;
            float b0 = bias[col], b1 = bias[col + 1];
            int r0 = m0 + wm * 32 + mi * 16 + crow;
            float2 v0 = make_float2(acc[mi][ni][0] + b0, acc[mi][ni][1] + b1);
            float2 v1 = make_float2(acc[mi][ni][2] + b0, acc[mi][ni][3] + b1);
            *(float2*)(C + (size_t)r0 * N + col)       = v0;
            *(float2*)(C + (size_t)(r0 + 8) * N + col) = v1;
        }
    }
}

// ---------------------------------------------------------------------------
// Merged decompose: hidden (hi only) + qkv_w (hi/lo) + proj_w (hi/lo)
// ---------------------------------------------------------------------------
#define HID4 (SEQ * DIM / 4)
#define WQ4  (QKV_DIM * DIM / 4)
#define WP4  (DIM * DIM / 4)

__global__ void __launch_bounds__(256) decomp_all_kernel(
    const float4* __restrict__ hid, const float4* __restrict__ wq,
    const float4* __restrict__ wp,
    uint32_t* __restrict__ hidH,
    uint32_t* __restrict__ wqH, uint32_t* __restrict__ wqL,
    uint32_t* __restrict__ wpH, uint32_t* __restrict__ wpL)
{
    int idx = blockIdx.x * blockDim.x + threadIdx.x;
    if (idx < HID4) {
        float4 v = hid[idx];
        hidH[idx * 2]     = pack_h2(v.x, v.y);
        hidH[idx * 2 + 1] = pack_h2(v.z, v.w);
        return;
    }
    const float4* src;
    uint32_t *dh, *dl;
    int j;
    if (idx < HID4 + WQ4) {
        j = idx - HID4;  src = wq; dh = wqH; dl = wqL;
    } else if (idx < HID4 + WQ4 + WP4) {
        j = idx - HID4 - WQ4;  src = wp; dh = wpH; dl = wpL;
    } else return;

    float4 v = src[j];
    __half h0 = __float2half_rn(v.x);
    __half h1 = __float2half_rn(v.y);
    __half h2 = __float2half_rn(v.z);
    __half h3 = __float2half_rn(v.w);
    dh[j * 2]     = pack_h2(v.x, v.y);
    dh[j * 2 + 1] = pack_h2(v.z, v.w);
    dl[j * 2]     = pack_h2(v.x - __half2float(h0), v.y - __half2float(h1));
    dl[j * 2 + 1] = pack_h2(v.z - __half2float(h2), v.w - __half2float(h3));
}

// ---------------------------------------------------------------------------
// Balanced merged prep: blocks [0,512) = V transpose, [512,832) = Q/K rope.
// Q/K now single fp16 planes.
// ---------------------------------------------------------------------------
__global__ void __launch_bounds__(256) prep_kernel(const float* __restrict__ rot)
{
    const int tid = threadIdx.x;
    const int bid = blockIdx.x;

    if (bid < 512) {
        __shared__ float T[HEAD_DIM][65];
        const int h  = bid & 15;
        const int s0 = (bid >> 4) * 64;
        #pragma unroll
        for (int i = 0; i < 20; i++) {
            int idx = tid + i * 256;
            int r = idx / HEAD_DIM, d = idx % HEAD_DIM;
            T[d][r] = g_qkv[(size_t)(s0 + r) * QKV_DIM + 2 * DIM + h * HEAD_DIM + d];
        }
        __syncthreads();
        #pragma unroll
        for (int i = 0; i < 20; i++) {
            int idx = tid + i * 256;
            int d = idx / 64, r = idx % 64;
            size_t o = ((size_t)h * HEAD_DIM + d) * SEQ + s0 + r;
            g_vt_h[o] = __float2half_rn(T[d][r]);
        }
    } else {
        int t = (bid - 512) * 256 + tid;
        if (t >= SEQ * 40) return;
        int d2 = t % 40;
        int s  = t / 40;

        float f = rot[s * 40 + d2];
        float si, co;
        sincosf(f, &si, &co);
        const float scale = rsqrtf((float)HEAD_DIM);

        #pragma unroll 4
        for (int h = 0; h < HEADS; h++) {
            size_t qb = (size_t)s * QKV_DIM + h * HEAD_DIM;
            float q1 = g_qkv[qb + d2],        q2 = g_qkv[qb + 40 + d2];
            float k1 = g_qkv[qb + DIM + d2],  k2 = g_qkv[qb + DIM + 40 + d2];

            float qr1 = (q1 * co - q2 * si) * scale;
            float qr2 = (q2 * co + q1 * si) * scale;
            float kr1 = k1 * co - k2 * si;
            float kr2 = k2 * co + k1 * si;

            size_t ob = ((size_t)h * SEQ + s) * HEAD_DIM;
            g_q_h[ob + d2]      = __float2half_rn(qr1);
            g_q_h[ob + 40 + d2] = __float2half_rn(qr2);
            g_k_h[ob + d2]      = __float2half_rn(kr1);
            g_k_h[ob + 40 + d2] = __float2half_rn(kr2);
        }
    }
}

// ---------------------------------------------------------------------------
// Tensor-core flash attention: AK=32, 2 CTAs/SM, nomask fast path,
// QK fp16 1-term, PV fp16 2-term.
// ---------------------------------------------------------------------------
#define AQ    128
#define AK    32
#define QSTR  88
#define VSTR  40
#define QPL   (AQ * QSTR * 2)        // 22528 (single plane)
#define KPL   (AK * QSTR * 2)        // 5632  (single plane per stage)
#define VPL   (HEAD_DIM * VSTR * 2)  // 6400  (single plane per stage)
#define FA_SMEM (QPL + 2*KPL + 2*VPL + (AQ + 2*AK + 8) * 4)

__global__ void __launch_bounds__(256, 2) fattn_kernel(const int* __restrict__ cu, int ncu)
{
    extern __shared__ char smraw[];
    char* Qb  = smraw;
    char* Kb  = Qb + QPL;
    char* Vb  = Kb + 2 * KPL;
    int* segq  = (int*)(Vb + 2 * VPL);
    int* segk  = segq + AQ;
    int* range = segk + 2 * AK;        // [0]=lo [1]=hi [2]=nomask

    const int tid = threadIdx.x;
    const int w   = tid >> 5;
    const int ln  = tid & 31;
    const int head  = blockIdx.y;
    const int qbase = blockIdx.x * AQ;

    // Q plane: 1280 chunks of 16B, 5 per thread
    {
        const uint32_t qs = smem_u32(Qb);
        #pragma unroll
        for (int i = 0; i < 5; i++) {
            int idx = tid + i * 256;
            int r = idx / 10, c = idx % 10;
            CP_ASYNC16(qs + (uint32_t)(r * QSTR + c * 8) * 2,
                       g_q_h + ((size_t)head * SEQ + qbase + r) * HEAD_DIM + c * 8);
        }
        CP_COMMIT();
    }
    if (tid < AQ) {
        int i = qbase + tid;
        int s = 0;
        for (int j = 1; j < ncu; j++) s += (cu[j] <= i);
        segq[tid] = s;
    }
    __syncthreads();
    if (tid == 0) {
        int smin = segq[0], smax = segq[AQ - 1];
        for (int r = 1; r < AQ; r++) { smin = min(smin, segq[r]); smax = max(smax, segq[r]); }
        int lo = cu[smin], hi = cu[smax + 1];
        range[0] = lo;
        range[1] = hi;
        range[2] = (smin == smax) && (((hi - lo) % AK) == 0);
    }
    __syncthreads();
    const int lo = range[0], hi_ = range[1];
    const bool nomask = (range[2] != 0);

    // K/V loader: K 320 chunks + V 320 chunks = 640, 3 iters
    auto load_kv = [&](int kt, int st) {
        const uint32_t ks = smem_u32(Kb) + st * KPL;
        const uint32_t vs = smem_u32(Vb) + st * VPL;
        #pragma unroll
        for (int i = 0; i < 3; i++) {
            int idx = tid + i * 256;
            if (idx < 320) {
                int r = idx / 10, c = idx % 10;
                int row = min(kt + r, SEQ - 1);
                CP_ASYNC16(ks + (uint32_t)(r * QSTR + c * 8) * 2,
                           g_k_h + ((size_t)head * SEQ + row) * HEAD_DIM + c * 8);
            } else if (idx < 640) {
                int j = idx - 320;
                int d = j / 4, c = j % 4;
                int col = min(kt + c * 8, SEQ - 8);
                CP_ASYNC16(vs + (uint32_t)(d * VSTR + c * 8) * 2,
                           g_vt_h + ((size_t)head * HEAD_DIM + d) * SEQ + col);
            }
        }
        CP_COMMIT();
    };

    const int qr = ln >> 2;
    const int kq = (ln & 3) * 2;
    const int row0 = w * 16 + qr;
    const int row1 = row0 + 8;
    const int sq0 = segq[row0], sq1 = segq[row1];

    float m0 = -1e30f, m1 = -1e30f, l0 = 0.f, l1 = 0.f;
    float acc[10][4];
    #pragma unroll
    for (int n = 0; n < 10; n++)
        #pragma unroll
        for (int c = 0; c < 4; c++) acc[n][c] = 0.f;

    const int a_row = (ln & 15);
    const int a_kof = (ln < 16) ? 0 : 8;
    const int b_row = (ln & 7);
    const int b_kof = (ln & 8);

    load_kv(lo, 0);
    CP_WAIT(0);
    __syncthreads();

    int st = 0;
    for (int kt = lo; kt < hi_; kt += AK) {
        const bool hasNext = (kt + AK) < hi_;
        if (hasNext) load_kv(kt + AK, st ^ 1);

        if (!nomask && tid < AK) {
            int key = kt + tid;
            int s = -1;
            if (key < hi_) {
                s = 0;
                for (int j = 1; j < ncu; j++) s += (cu[j] <= key);
            }
            segk[st * AK + tid] = s;
        }
        if (hasNext) { CP_WAIT(1); } else { CP_WAIT(0); }
        __syncthreads();

        const uint32_t pQ  = smem_u32(Qb);
        const uint32_t pKh = smem_u32(Kb) + st * KPL;
        const uint32_t pVh = smem_u32(Vb) + st * VPL;
        const int* sk = segk + st * AK;

        // ---- S = Q @ K^T, fp16 1-term ----
        float S[4][4];
        #pragma unroll
        for (int j = 0; j < 4; j++)
            #pragma unroll
            for (int c = 0; c < 4; c++) S[j][c] = 0.f;

        #pragma unroll
        for (int kc = 0; kc < 5; kc++) {
            uint32_t a0, a1, a2, a3;
            uint32_t qoff = (uint32_t)((w * 16 + a_row) * QSTR + kc * 16 + a_kof) * 2;
            LDSM_X4(a0, a1, a2, a3, pQ + qoff);
            uint32_t bh[4][2];
            #pragma unroll
            for (int q = 0; q < 4; q++) {
                uint32_t koff = (uint32_t)((q * 8 + b_row) * QSTR
                                           + kc * 16 + b_kof) * 2;
                LDSM_X2(bh[q][0], bh[q][1], pKh + koff);
            }
            #pragma unroll
            for (int q = 0; q < 4; q++)
                MMAH16816(S[q][0], S[q][1], S[q][2], S[q][3],
                          a0, a1, a2, a3, bh[q][0], bh[q][1]);
        }

        // ---- online softmax ----
        float mt0 = -1e30f, mt1 = -1e30f;
        float rs0 = 0.f, rs1 = 0.f;
        if (nomask) {
            #pragma unroll
            for (int j = 0; j < 4; j++) {
                mt0 = fmaxf(mt0, fmaxf(S[j][0], S[j][1]));
                mt1 = fmaxf(mt1, fmaxf(S[j][2], S[j][3]));
            }
            #pragma unroll
            for (int msk = 1; msk <= 2; msk <<= 1) {
                mt0 = fmaxf(mt0, __shfl_xor_sync(0xffffffffu, mt0, msk));
                mt1 = fmaxf(mt1, __shfl_xor_sync(0xffffffffu, mt1, msk));
            }
            float mn0 = fmaxf(m0, mt0), mn1 = fmaxf(m1, mt1);
            float alpha0 = __expf(m0 - mn0), alpha1 = __expf(m1 - mn1);
            #pragma unroll
            for (int j = 0; j < 4; j++) {
                float p0 = __expf(S[j][0] - mn0);
                float p1 = __expf(S[j][1] - mn0);
                float p2 = __expf(S[j][2] - mn1);
                float p3 = __expf(S[j][3] - mn1);
                S[j][0] = p0; S[j][1] = p1; S[j][2] = p2; S[j][3] = p3;
                rs0 += p0 + p1;
                rs1 += p2 + p3;
            }
            #pragma unroll
            for (int msk = 1; msk <= 2; msk <<= 1) {
                rs0 += __shfl_xor_sync(0xffffffffu, rs0, msk);
                rs1 += __shfl_xor_sync(0xffffffffu, rs1, msk);
            }
            l0 = l0 * alpha0 + rs0;
            l1 = l1 * alpha1 + rs1;
            m0 = mn0; m1 = mn1;
            #pragma unroll
            for (int n = 0; n < 10; n++) {
                acc[n][0] *= alpha0; acc[n][1] *= alpha0;
                acc[n][2] *= alpha1; acc[n][3] *= alpha1;
            }
        } else {
            #pragma unroll
            for (int j = 0; j < 4; j++) {
                int k0 = j * 8 + kq;
                int sk0 = sk[k0], sk1 = sk[k0 + 1];
                mt0 = fmaxf(mt0, (sk0 == sq0) ? S[j][0] : -1e30f);
                mt0 = fmaxf(mt0, (sk1 == sq0) ? S[j][1] : -1e30f);
                mt1 = fmaxf(mt1, (sk0 == sq1) ? S[j][2] : -1e30f);
                mt1 = fmaxf(mt1, (sk1 == sq1) ? S[j][3] : -1e30f);
            }
            #pragma unroll
            for (int msk = 1; msk <= 2; msk <<= 1) {
                mt0 = fmaxf(mt0, __shfl_xor_sync(0xffffffffu, mt0, msk));
                mt1 = fmaxf(mt1, __shfl_xor_sync(0xffffffffu, mt1, msk));
            }
            float mn0 = fmaxf(m0, mt0), mn1 = fmaxf(m1, mt1);
            float alpha0 = __expf(m0 - mn0), alpha1 = __expf(m1 - mn1);
            #pragma unroll
            for (int j = 0; j < 4; j++) {
                int k0 = j * 8 + kq;
                int sk0 = sk[k0], sk1 = sk[k0 + 1];
                float p0 = (sk0 == sq0) ? __expf(S[j][0] - mn0) : 0.f;
                float p1 = (sk1 == sq0) ? __expf(S[j][1] - mn0) : 0.f;
                float p2 = (sk0 == sq1) ? __expf(S[j][2] - mn1) : 0.f;
                float p3 = (sk1 == sq1) ? __expf(S[j][3] - mn1) : 0.f;
                S[j][0] = p0; S[j][1] = p1; S[j][2] = p2; S[j][3] = p3;
                rs0 += p0 + p1;
                rs1 += p2 + p3;
            }
            #pragma unroll
            for (int msk = 1; msk <= 2; msk <<= 1) {
                rs0 += __shfl_xor_sync(0xffffffffu, rs0, msk);
                rs1 += __shfl_xor_sync(0xffffffffu, rs1, msk);
            }
            l0 = l0 * alpha0 + rs0;
            l1 = l1 * alpha1 + rs1;
            m0 = mn0; m1 = mn1;
            #pragma unroll
            for (int n = 0; n < 10; n++) {
                acc[n][0] *= alpha0; acc[n][1] *= alpha0;
                acc[n][2] *= alpha1; acc[n][3] *= alpha1;
            }
        }

        // ---- O += P @ V, fp16 2-term (P hi/lo, V single plane) ----
        #pragma unroll
        for (int jc = 0; jc < 2; jc++) {
            float h00 = __half2float(__float2half_rn(S[2*jc][0]));
            float h01 = __half2float(__float2half_rn(S[2*jc][1]));
            float h02 = __half2float(__float2half_rn(S[2*jc][2]));
            float h03 = __half2float(__float2half_rn(S[2*jc][3]));
            float h10 = __half2float(__float2half_rn(S[2*jc+1][0]));
            float h11 = __half2float(__float2half_rn(S[2*jc+1][1]));
            float h12 = __half2float(__float2half_rn(S[2*jc+1][2]));
            float h13 = __half2float(__float2half_rn(S[2*jc+1][3]));
            uint32_t aPh[4], aPl[4];
            aPh[0] = pack_h2(h00, h01);
            aPh[1] = pack_h2(h02, h03);
            aPh[2] = pack_h2(h10, h11);
            aPh[3] = pack_h2(h12, h13);
            aPl[0] = pack_h2(S[2*jc][0] - h00, S[2*jc][1] - h01);
            aPl[1] = pack_h2(S[2*jc][2] - h02, S[2*jc][3] - h03);
            aPl[2] = pack_h2(S[2*jc+1][0] - h10, S[2*jc+1][1] - h11);
            aPl[3] = pack_h2(S[2*jc+1][2] - h12, S[2*jc+1][3] - h13);

            #pragma unroll
            for (int ng = 0; ng < 3; ng++) {
                const int gs = ng * 4;
                const int gn = (ng == 2) ? 2 : 4;
                uint32_t bh[4][2];
                #pragma unroll
                for (int q = 0; q < 4; q++) {
                    if (q < gn) {
                        uint32_t voff = (uint32_t)(((gs + q) * 8 + b_row) * VSTR
                                                   + jc * 16 + b_kof) * 2;
                        LDSM_X2(bh[q][0], bh[q][1], pVh + voff);
                    }
                }
                #pragma unroll
                for (int q = 0; q < 4; q++)
                    if (q < gn)
                        MMAH16816(acc[gs+q][0], acc[gs+q][1], acc[gs+q][2], acc[gs+q][3],
                                  aPh[0], aPh[1], aPh[2], aPh[3], bh[q][0], bh[q][1]);
                #pragma unroll
                for (int q = 0; q < 4; q++)
                    if (q < gn)
                        MMAH16816(acc[gs+q][0], acc[gs+q][1], acc[gs+q][2], acc[gs+q][3],
                                  aPl[0], aPl[1], aPl[2], aPl[3], bh[q][0], bh[q][1]);
            }
        }

        __syncthreads();
        st ^= 1;
    }

    float il0 = (l0 > 0.f) ? (1.f / l0) : 0.f;
    float il1 = (l1 > 0.f) ? (1.f / l1) : 0.f;
    #pragma unroll
    for (int n = 0; n < 10; n++) {
        int d = n * 8 + kq;
        size_t o0 = (size_t)(qbase + row0) * DIM + head * HEAD_DIM + d;
        size_t o1 = (size_t)(qbase + row1) * DIM + head * HEAD_DIM + d;
        *(uint32_t*)&g_at_h[o0] = pack_h2(acc[n][0] * il0, acc[n][1] * il0);
        *(uint32_t*)&g_at_h[o1] = pack_h2(acc[n][2] * il1, acc[n][3] * il1);
    }
}

// ---------------------------------------------------------------------------
extern "C" void kernel_launch(void* const* d_in, const int* in_sizes, int n_in,
                              void* d_out, int out_size)
{
    const float* hidden = (const float*)d_in[0];
    const float* rotary = (const float*)d_in[1];
    const int*   cu     = (const int*)d_in[2];
    const float* qkv_w  = (const float*)d_in[3];
    const float* qkv_b  = (const float*)d_in[4];
    const float* proj_w = (const float*)d_in[5];
    const float* proj_b = (const float*)d_in[6];
    float* out = (float*)d_out;
    int ncu = in_sizes[2];

    float *qkv_ptr;
    __half *hidH, *wqH, *wqL, *wpH, *wpL, *atH;
    cudaGetSymbolAddress((void**)&qkv_ptr, g_qkv);
    cudaGetSymbolAddress((void**)&hidH, g_hid_h);
    cudaGetSymbolAddress((void**)&wqH, g_wq_h);
    cudaGetSymbolAddress((void**)&wqL, g_wq_l);
    cudaGetSymbolAddress((void**)&wpH, g_wp_h);
    cudaGetSymbolAddress((void**)&wpL, g_wp_l);
    cudaGetSymbolAddress((void**)&atH, g_at_h);

    cudaFuncSetAttribute(hgemm2_kernel,
                         cudaFuncAttributeMaxDynamicSharedMemorySize, HG_SMEM);

    // 0) Merged decomposition
    {
        int total = HID4 + WQ4 + WP4;
        decomp_all_kernel<<<(total + 255) / 256, 256>>>(
            (const float4*)hidden, (const float4*)qkv_w, (const float4*)proj_w,
            (uint32_t*)hidH, (uint32_t*)wqH, (uint32_t*)wqL,
            (uint32_t*)wpH, (uint32_t*)wpL);
    }

    // 1) QKV GEMM
    hgemm2_kernel<<<dim3(QKV_DIM / 64, SEQ / 128), 256, HG_SMEM>>>(
        hidH, wqH, wqL, qkv_b, qkv_ptr, SEQ, QKV_DIM, DIM);

    // 2) Balanced merged prep
    prep_kernel<<<832, 256>>>(rotary);

    // 3) Flash attention (QK 1-term fp16, PV 2-term fp16)
    {
        cudaFuncSetAttribute(fattn_kernel,
                             cudaFuncAttributeMaxDynamicSharedMemorySize, FA_SMEM);
        fattn_kernel<<<dim3(SEQ / AQ, HEADS), 256, FA_SMEM>>>(cu, ncu);
    }

    // 4) proj GEMM
    hgemm2_kernel<<<dim3(DIM / 64, SEQ / 128), 256, HG_SMEM>>>(
        atH, wpH, wpL, proj_b, out, SEQ, DIM, DIM);
}

// round 17
// speedup vs baseline: 1.8807x; 1.3663x over previous
#include <cuda_runtime.h>
#include <cuda_bf16.h>
#include <cuda_fp16.h>
#include <math.h>
#include <stdint.h>

#define SEQ      2048
#define DIM      1280
#define HEADS    16
#define HEAD_DIM 80
#define QKV_DIM  3840

// ---------------------------------------------------------------------------
// Scratch
// ---------------------------------------------------------------------------
__device__ float g_qkv[SEQ * QKV_DIM];
__device__ __half g_hid_h[SEQ * DIM];
__device__ __half g_wq_h[QKV_DIM * DIM];
__device__ __half g_wp_h[DIM * DIM];
__device__ __half g_at_h[SEQ * DIM];
__device__ __half g_q_h[HEADS * SEQ * HEAD_DIM];
__device__ __half g_k_h[HEADS * SEQ * HEAD_DIM];
__device__ __half g_vt_h[HEADS * HEAD_DIM * SEQ];

// ---------------------------------------------------------------------------
// PTX helpers
// ---------------------------------------------------------------------------
#define CP_ASYNC16(dst, src) \
    asm volatile("cp.async.cg.shared.global [%0], [%1], 16;" :: "r"(dst), "l"(src))
#define CP_COMMIT() asm volatile("cp.async.commit_group;")
#define CP_WAIT(n)  asm volatile("cp.async.wait_group %0;" :: "n"(n))

#define LDSM_X4(r0,r1,r2,r3,addr) \
    asm volatile("ldmatrix.sync.aligned.m8n8.x4.shared.b16 {%0,%1,%2,%3}, [%4];" \
        : "=r"(r0),"=r"(r1),"=r"(r2),"=r"(r3) : "r"(addr))
#define LDSM_X2(r0,r1,addr) \
    asm volatile("ldmatrix.sync.aligned.m8n8.x2.shared.b16 {%0,%1}, [%2];" \
        : "=r"(r0),"=r"(r1) : "r"(addr))

#define MMAH16816(c0,c1,c2,c3,a0,a1,a2,a3,b0,b1) \
    asm volatile("mma.sync.aligned.m16n8k16.row.col.f32.f16.f16.f32 " \
        "{%0,%1,%2,%3}, {%4,%5,%6,%7}, {%8,%9}, {%0,%1,%2,%3};" \
        : "+f"(c0),"+f"(c1),"+f"(c2),"+f"(c3) \
        : "r"(a0),"r"(a1),"r"(a2),"r"(a3),"r"(b0),"r"(b1))

__device__ __forceinline__ uint32_t smem_u32(const void* p) {
    return (uint32_t)__cvta_generic_to_shared(p);
}
__device__ __forceinline__ uint32_t pack_h2(float a, float b) {
    __half2 v = __floats2half2_rn(a, b);
    return *(uint32_t*)&v;
}

// ---------------------------------------------------------------------------
// Plain fp16 HGEMM (TN): C = A @ B^T + bias, fp32 accum.
// Block tile 128x64, 8 warps (4x2), warp tile 32x32, KBLK=32 double-buffered.
// ---------------------------------------------------------------------------
#define KBLK 32
#define KPAD 40
#define APLANE_B (128 * KPAD * 2)              // 10240
#define BPLANE_B (64 * KPAD * 2)               // 5120
#define STAGE_B (APLANE_B + BPLANE_B)          // 15360
#define HG_SMEM (2 * STAGE_B)                  // 30720

__global__ void __launch_bounds__(256, 3) hgemm1_kernel(
    const __half* __restrict__ Ah_, const __half* __restrict__ Bh_,
    const float* __restrict__ bias, float* __restrict__ C,
    int M, int N, int K)
{
    extern __shared__ char smraw[];
    const uint32_t sb = smem_u32(smraw);

    const int tid = threadIdx.x;
    const int ln  = tid & 31;
    const int wid = tid >> 5;
    const int wm  = wid >> 1;
    const int wn  = wid & 1;
    const int m0  = blockIdx.y * 128;
    const int n0  = blockIdx.x * 64;

    const __half* gA = Ah_ + (size_t)m0 * K;
    const __half* gB = Bh_ + (size_t)n0 * K;

    const int arow0 = tid >> 2;
    const int arow1 = (tid + 256) >> 2;
    const int brow  = tid >> 2;
    const int kc16  = (tid & 3) * 8;

    auto load_stage = [&](int kt, int s) {
        const uint32_t stb = sb + s * STAGE_B;
        CP_ASYNC16(stb + (uint32_t)(arow0 * KPAD + kc16) * 2,
                   gA + (size_t)arow0 * K + kt + kc16);
        CP_ASYNC16(stb + (uint32_t)(arow1 * KPAD + kc16) * 2,
                   gA + (size_t)arow1 * K + kt + kc16);
        CP_ASYNC16(stb + APLANE_B + (uint32_t)(brow * KPAD + kc16) * 2,
                   gB + (size_t)brow * K + kt + kc16);
        CP_COMMIT();
    };

    float acc[2][4][4];
    #pragma unroll
    for (int mi = 0; mi < 2; mi++)
        #pragma unroll
        for (int ni = 0; ni < 4; ni++)
            #pragma unroll
            for (int c = 0; c < 4; c++) acc[mi][ni][c] = 0.f;

    load_stage(0, 0);
    CP_WAIT(0);
    __syncthreads();

    const int a_row = (ln & 15);
    const int a_kof = (ln < 16) ? 0 : 8;
    const int b_row = (ln & 7);
    const int b_kof = (ln & 8);

    int buf = 0;
    for (int kt = 0; kt < K; kt += KBLK) {
        const bool hasNext = (kt + KBLK) < K;
        if (hasNext) load_stage(kt + KBLK, buf ^ 1);

        const uint32_t stb = sb + buf * STAGE_B;
        const uint32_t pAh = stb;
        const uint32_t pBh = stb + APLANE_B;

        #pragma unroll
        for (int ks = 0; ks < 2; ks++) {
            const int k0 = ks * 16;
            uint32_t ah[2][4];
            #pragma unroll
            for (int mi = 0; mi < 2; mi++) {
                uint32_t off = (uint32_t)((wm * 32 + mi * 16 + a_row) * KPAD
                                          + k0 + a_kof) * 2;
                LDSM_X4(ah[mi][0], ah[mi][1], ah[mi][2], ah[mi][3], pAh + off);
            }
            uint32_t bh[4][2];
            #pragma unroll
            for (int ni = 0; ni < 4; ni++) {
                uint32_t off = (uint32_t)((wn * 32 + ni * 8 + b_row) * KPAD
                                          + k0 + b_kof) * 2;
                LDSM_X2(bh[ni][0], bh[ni][1], pBh + off);
            }
            #pragma unroll
            for (int ni = 0; ni < 4; ni++)
                #pragma unroll
                for (int mi = 0; mi < 2; mi++)
                    MMAH16816(acc[mi][ni][0], acc[mi][ni][1],
                              acc[mi][ni][2], acc[mi][ni][3],
                              ah[mi][0], ah[mi][1], ah[mi][2], ah[mi][3],
                              bh[ni][0], bh[ni][1]);
        }

        if (hasNext) {
            CP_WAIT(0);
            __syncthreads();
            buf ^= 1;
        }
    }

    const int crow = ln >> 2;
    const int ccol = (ln & 3) * 2;
    #pragma unroll
    for (int mi = 0; mi < 2; mi++) {
        #pragma unroll
        for (int ni = 0; ni < 4; ni++) {
            int col = n0 + wn * 32 + ni * 8 + ccol;
            float b0 = bias[col], b1 = bias[col + 1];
            int r0 = m0 + wm * 32 + mi * 16 + crow;
            float2 v0 = make_float2(acc[mi][ni][0] + b0, acc[mi][ni][1] + b1);
            float2 v1 = make_float2(acc[mi][ni][2] + b0, acc[mi][ni][3] + b1);
            *(float2*)(C + (size_t)r0 * N + col)       = v0;
            *(float2*)(C + (size_t)(r0 + 8) * N + col) = v1;
        }
    }
}

// ---------------------------------------------------------------------------
// Merged decompose: all three inputs -> fp16 hi planes only
// ---------------------------------------------------------------------------
#define HID4 (SEQ * DIM / 4)
#define WQ4  (QKV_DIM * DIM / 4)
#define WP4  (DIM * DIM / 4)

__global__ void __launch_bounds__(256) decomp_all_kernel(
    const float4* __restrict__ hid, const float4* __restrict__ wq,
    const float4* __restrict__ wp,
    uint32_t* __restrict__ hidH, uint32_t* __restrict__ wqH,
    uint32_t* __restrict__ wpH)
{
    int idx = blockIdx.x * blockDim.x + threadIdx.x;
    const float4* src;
    uint32_t* dh;
    int j;
    if (idx < HID4)                 { j = idx;               src = hid; dh = hidH; }
    else if (idx < HID4 + WQ4)      { j = idx - HID4;        src = wq;  dh = wqH;  }
    else if (idx < HID4 + WQ4 + WP4){ j = idx - HID4 - WQ4;  src = wp;  dh = wpH;  }
    else return;

    float4 v = src[j];
    dh[j * 2]     = pack_h2(v.x, v.y);
    dh[j * 2 + 1] = pack_h2(v.z, v.w);
}

// ---------------------------------------------------------------------------
// Balanced merged prep: blocks [0,512) = V transpose, [512,832) = Q/K rope.
// ---------------------------------------------------------------------------
__global__ void __launch_bounds__(256) prep_kernel(const float* __restrict__ rot)
{
    const int tid = threadIdx.x;
    const int bid = blockIdx.x;

    if (bid < 512) {
        __shared__ float T[HEAD_DIM][65];
        const int h  = bid & 15;
        const int s0 = (bid >> 4) * 64;
        #pragma unroll
        for (int i = 0; i < 20; i++) {
            int idx = tid + i * 256;
            int r = idx / HEAD_DIM, d = idx % HEAD_DIM;
            T[d][r] = g_qkv[(size_t)(s0 + r) * QKV_DIM + 2 * DIM + h * HEAD_DIM + d];
        }
        __syncthreads();
        #pragma unroll
        for (int i = 0; i < 20; i++) {
            int idx = tid + i * 256;
            int d = idx / 64, r = idx % 64;
            size_t o = ((size_t)h * HEAD_DIM + d) * SEQ + s0 + r;
            g_vt_h[o] = __float2half_rn(T[d][r]);
        }
    } else {
        int t = (bid - 512) * 256 + tid;
        if (t >= SEQ * 40) return;
        int d2 = t % 40;
        int s  = t / 40;

        float f = rot[s * 40 + d2];
        float si, co;
        sincosf(f, &si, &co);
        const float scale = rsqrtf((float)HEAD_DIM);

        #pragma unroll 4
        for (int h = 0; h < HEADS; h++) {
            size_t qb = (size_t)s * QKV_DIM + h * HEAD_DIM;
            float q1 = g_qkv[qb + d2],        q2 = g_qkv[qb + 40 + d2];
            float k1 = g_qkv[qb + DIM + d2],  k2 = g_qkv[qb + DIM + 40 + d2];

            float qr1 = (q1 * co - q2 * si) * scale;
            float qr2 = (q2 * co + q1 * si) * scale;
            float kr1 = k1 * co - k2 * si;
            float kr2 = k2 * co + k1 * si;

            size_t ob = ((size_t)h * SEQ + s) * HEAD_DIM;
            g_q_h[ob + d2]      = __float2half_rn(qr1);
            g_q_h[ob + 40 + d2] = __float2half_rn(qr2);
            g_k_h[ob + d2]      = __float2half_rn(kr1);
            g_k_h[ob + 40 + d2] = __float2half_rn(kr2);
        }
    }
}

// ---------------------------------------------------------------------------
// Tensor-core flash attention (round-16, unchanged): AK=32, 2 CTAs/SM,
// nomask fast path, QK fp16 1-term, PV fp16 2-term.
// ---------------------------------------------------------------------------
#define AQ    128
#define AK    32
#define QSTR  88
#define VSTR  40
#define QPL   (AQ * QSTR * 2)
#define KPL   (AK * QSTR * 2)
#define VPL   (HEAD_DIM * VSTR * 2)
#define FA_SMEM (QPL + 2*KPL + 2*VPL + (AQ + 2*AK + 8) * 4)

__global__ void __launch_bounds__(256, 2) fattn_kernel(const int* __restrict__ cu, int ncu)
{
    extern __shared__ char smraw[];
    char* Qb  = smraw;
    char* Kb  = Qb + QPL;
    char* Vb  = Kb + 2 * KPL;
    int* segq  = (int*)(Vb + 2 * VPL);
    int* segk  = segq + AQ;
    int* range = segk + 2 * AK;

    const int tid = threadIdx.x;
    const int w   = tid >> 5;
    const int ln  = tid & 31;
    const int head  = blockIdx.y;
    const int qbase = blockIdx.x * AQ;

    {
        const uint32_t qs = smem_u32(Qb);
        #pragma unroll
        for (int i = 0; i < 5; i++) {
            int idx = tid + i * 256;
            int r = idx / 10, c = idx % 10;
            CP_ASYNC16(qs + (uint32_t)(r * QSTR + c * 8) * 2,
                       g_q_h + ((size_t)head * SEQ + qbase + r) * HEAD_DIM + c * 8);
        }
        CP_COMMIT();
    }
    if (tid < AQ) {
        int i = qbase + tid;
        int s = 0;
        for (int j = 1; j < ncu; j++) s += (cu[j] <= i);
        segq[tid] = s;
    }
    __syncthreads();
    if (tid == 0) {
        int smin = segq[0], smax = segq[AQ - 1];
        for (int r = 1; r < AQ; r++) { smin = min(smin, segq[r]); smax = max(smax, segq[r]); }
        int lo = cu[smin], hi = cu[smax + 1];
        range[0] = lo;
        range[1] = hi;
        range[2] = (smin == smax) && (((hi - lo) % AK) == 0);
    }
    __syncthreads();
    const int lo = range[0], hi_ = range[1];
    const bool nomask = (range[2] != 0);

    auto load_kv = [&](int kt, int st) {
        const uint32_t ks = smem_u32(Kb) + st * KPL;
        const uint32_t vs = smem_u32(Vb) + st * VPL;
        #pragma unroll
        for (int i = 0; i < 3; i++) {
            int idx = tid + i * 256;
            if (idx < 320) {
                int r = idx / 10, c = idx % 10;
                int row = min(kt + r, SEQ - 1);
                CP_ASYNC16(ks + (uint32_t)(r * QSTR + c * 8) * 2,
                           g_k_h + ((size_t)head * SEQ + row) * HEAD_DIM + c * 8);
            } else if (idx < 640) {
                int j = idx - 320;
                int d = j / 4, c = j % 4;
                int col = min(kt + c * 8, SEQ - 8);
                CP_ASYNC16(vs + (uint32_t)(d * VSTR + c * 8) * 2,
                           g_vt_h + ((size_t)head * HEAD_DIM + d) * SEQ + col);
            }
        }
        CP_COMMIT();
    };

    const int qr = ln >> 2;
    const int kq = (ln & 3) * 2;
    const int row0 = w * 16 + qr;
    const int row1 = row0 + 8;
    const int sq0 = segq[row0], sq1 = segq[row1];

    float m0 = -1e30f, m1 = -1e30f, l0 = 0.f, l1 = 0.f;
    float acc[10][4];
    #pragma unroll
    for (int n = 0; n < 10; n++)
        #pragma unroll
        for (int c = 0; c < 4; c++) acc[n][c] = 0.f;

    const int a_row = (ln & 15);
    const int a_kof = (ln < 16) ? 0 : 8;
    const int b_row = (ln & 7);
    const int b_kof = (ln & 8);

    load_kv(lo, 0);
    CP_WAIT(0);
    __syncthreads();

    int st = 0;
    for (int kt = lo; kt < hi_; kt += AK) {
        const bool hasNext = (kt + AK) < hi_;
        if (hasNext) load_kv(kt + AK, st ^ 1);

        if (!nomask && tid < AK) {
            int key = kt + tid;
            int s = -1;
            if (key < hi_) {
                s = 0;
                for (int j = 1; j < ncu; j++) s += (cu[j] <= key);
            }
            segk[st * AK + tid] = s;
        }
        if (hasNext) { CP_WAIT(1); } else { CP_WAIT(0); }
        __syncthreads();

        const uint32_t pQ  = smem_u32(Qb);
        const uint32_t pKh = smem_u32(Kb) + st * KPL;
        const uint32_t pVh = smem_u32(Vb) + st * VPL;
        const int* sk = segk + st * AK;

        float S[4][4];
        #pragma unroll
        for (int j = 0; j < 4; j++)
            #pragma unroll
            for (int c = 0; c < 4; c++) S[j][c] = 0.f;

        #pragma unroll
        for (int kc = 0; kc < 5; kc++) {
            uint32_t a0, a1, a2, a3;
            uint32_t qoff = (uint32_t)((w * 16 + a_row) * QSTR + kc * 16 + a_kof) * 2;
            LDSM_X4(a0, a1, a2, a3, pQ + qoff);
            uint32_t bh[4][2];
            #pragma unroll
            for (int q = 0; q < 4; q++) {
                uint32_t koff = (uint32_t)((q * 8 + b_row) * QSTR
                                           + kc * 16 + b_kof) * 2;
                LDSM_X2(bh[q][0], bh[q][1], pKh + koff);
            }
            #pragma unroll
            for (int q = 0; q < 4; q++)
                MMAH16816(S[q][0], S[q][1], S[q][2], S[q][3],
                          a0, a1, a2, a3, bh[q][0], bh[q][1]);
        }

        float mt0 = -1e30f, mt1 = -1e30f;
        float rs0 = 0.f, rs1 = 0.f;
        if (nomask) {
            #pragma unroll
            for (int j = 0; j < 4; j++) {
                mt0 = fmaxf(mt0, fmaxf(S[j][0], S[j][1]));
                mt1 = fmaxf(mt1, fmaxf(S[j][2], S[j][3]));
            }
            #pragma unroll
            for (int msk = 1; msk <= 2; msk <<= 1) {
                mt0 = fmaxf(mt0, __shfl_xor_sync(0xffffffffu, mt0, msk));
                mt1 = fmaxf(mt1, __shfl_xor_sync(0xffffffffu, mt1, msk));
            }
            float mn0 = fmaxf(m0, mt0), mn1 = fmaxf(m1, mt1);
            float alpha0 = __expf(m0 - mn0), alpha1 = __expf(m1 - mn1);
            #pragma unroll
            for (int j = 0; j < 4; j++) {
                float p0 = __expf(S[j][0] - mn0);
                float p1 = __expf(S[j][1] - mn0);
                float p2 = __expf(S[j][2] - mn1);
                float p3 = __expf(S[j][3] - mn1);
                S[j][0] = p0; S[j][1] = p1; S[j][2] = p2; S[j][3] = p3;
                rs0 += p0 + p1;
                rs1 += p2 + p3;
            }
            #pragma unroll
            for (int msk = 1; msk <= 2; msk <<= 1) {
                rs0 += __shfl_xor_sync(0xffffffffu, rs0, msk);
                rs1 += __shfl_xor_sync(0xffffffffu, rs1, msk);
            }
            l0 = l0 * alpha0 + rs0;
            l1 = l1 * alpha1 + rs1;
            m0 = mn0; m1 = mn1;
            #pragma unroll
            for (int n = 0; n < 10; n++) {
                acc[n][0] *= alpha0; acc[n][1] *= alpha0;
                acc[n][2] *= alpha1; acc[n][3] *= alpha1;
            }
        } else {
            #pragma unroll
            for (int j = 0; j < 4; j++) {
                int k0 = j * 8 + kq;
                int sk0 = sk[k0], sk1 = sk[k0 + 1];
                mt0 = fmaxf(mt0, (sk0 == sq0) ? S[j][0] : -1e30f);
                mt0 = fmaxf(mt0, (sk1 == sq0) ? S[j][1] : -1e30f);
                mt1 = fmaxf(mt1, (sk0 == sq1) ? S[j][2] : -1e30f);
                mt1 = fmaxf(mt1, (sk1 == sq1) ? S[j][3] : -1e30f);
            }
            #pragma unroll
            for (int msk = 1; msk <= 2; msk <<= 1) {
                mt0 = fmaxf(mt0, __shfl_xor_sync(0xffffffffu, mt0, msk));
                mt1 = fmaxf(mt1, __shfl_xor_sync(0xffffffffu, mt1, msk));
            }
            float mn0 = fmaxf(m0, mt0), mn1 = fmaxf(m1, mt1);
            float alpha0 = __expf(m0 - mn0), alpha1 = __expf(m1 - mn1);
            #pragma unroll
            for (int j = 0; j < 4; j++) {
                int k0 = j * 8 + kq;
                int sk0 = sk[k0], sk1 = sk[k0 + 1];
                float p0 = (sk0 == sq0) ? __expf(S[j][0] - mn0) : 0.f;
                float p1 = (sk1 == sq0) ? __expf(S[j][1] - mn0) : 0.f;
                float p2 = (sk0 == sq1) ? __expf(S[j][2] - mn1) : 0.f;
                float p3 = (sk1 == sq1) ? __expf(S[j][3] - mn1) : 0.f;
                S[j][0] = p0; S[j][1] = p1; S[j][2] = p2; S[j][3] = p3;
                rs0 += p0 + p1;
                rs1 += p2 + p3;
            }
            #pragma unroll
            for (int msk = 1; msk <= 2; msk <<= 1) {
                rs0 += __shfl_xor_sync(0xffffffffu, rs0, msk);
                rs1 += __shfl_xor_sync(0xffffffffu, rs1, msk);
            }
            l0 = l0 * alpha0 + rs0;
            l1 = l1 * alpha1 + rs1;
            m0 = mn0; m1 = mn1;
            #pragma unroll
            for (int n = 0; n < 10; n++) {
                acc[n][0] *= alpha0; acc[n][1] *= alpha0;
                acc[n][2] *= alpha1; acc[n][3] *= alpha1;
            }
        }

        #pragma unroll
        for (int jc = 0; jc < 2; jc++) {
            float h00 = __half2float(__float2half_rn(S[2*jc][0]));
            float h01 = __half2float(__float2half_rn(S[2*jc][1]));
            float h02 = __half2float(__float2half_rn(S[2*jc][2]));
            float h03 = __half2float(__float2half_rn(S[2*jc][3]));
            float h10 = __half2float(__float2half_rn(S[2*jc+1][0]));
            float h11 = __half2float(__float2half_rn(S[2*jc+1][1]));
            float h12 = __half2float(__float2half_rn(S[2*jc+1][2]));
            float h13 = __half2float(__float2half_rn(S[2*jc+1][3]));
            uint32_t aPh[4], aPl[4];
            aPh[0] = pack_h2(h00, h01);
            aPh[1] = pack_h2(h02, h03);
            aPh[2] = pack_h2(h10, h11);
            aPh[3] = pack_h2(h12, h13);
            aPl[0] = pack_h2(S[2*jc][0] - h00, S[2*jc][1] - h01);
            aPl[1] = pack_h2(S[2*jc][2] - h02, S[2*jc][3] - h03);
            aPl[2] = pack_h2(S[2*jc+1][0] - h10, S[2*jc+1][1] - h11);
            aPl[3] = pack_h2(S[2*jc+1][2] - h12, S[2*jc+1][3] - h13);

            #pragma unroll
            for (int ng = 0; ng < 3; ng++) {
                const int gs = ng * 4;
                const int gn = (ng == 2) ? 2 : 4;
                uint32_t bh[4][2];
                #pragma unroll
                for (int q = 0; q < 4; q++) {
                    if (q < gn) {
                        uint32_t voff = (uint32_t)(((gs + q) * 8 + b_row) * VSTR
                                                   + jc * 16 + b_kof) * 2;
                        LDSM_X2(bh[q][0], bh[q][1], pVh + voff);
                    }
                }
                #pragma unroll
                for (int q = 0; q < 4; q++)
                    if (q < gn)
                        MMAH16816(acc[gs+q][0], acc[gs+q][1], acc[gs+q][2], acc[gs+q][3],
                                  aPh[0], aPh[1], aPh[2], aPh[3], bh[q][0], bh[q][1]);
                #pragma unroll
                for (int q = 0; q < 4; q++)
                    if (q < gn)
                        MMAH16816(acc[gs+q][0], acc[gs+q][1], acc[gs+q][2], acc[gs+q][3],
                                  aPl[0], aPl[1], aPl[2], aPl[3], bh[q][0], bh[q][1]);
            }
        }

        __syncthreads();
        st ^= 1;
    }

    float il0 = (l0 > 0.f) ? (1.f / l0) : 0.f;
    float il1 = (l1 > 0.f) ? (1.f / l1) : 0.f;
    #pragma unroll
    for (int n = 0; n < 10; n++) {
        int d = n * 8 + kq;
        size_t o0 = (size_t)(qbase + row0) * DIM + head * HEAD_DIM + d;
        size_t o1 = (size_t)(qbase + row1) * DIM + head * HEAD_DIM + d;
        *(uint32_t*)&g_at_h[o0] = pack_h2(acc[n][0] * il0, acc[n][1] * il0);
        *(uint32_t*)&g_at_h[o1] = pack_h2(acc[n][2] * il1, acc[n][3] * il1);
    }
}

// ---------------------------------------------------------------------------
extern "C" void kernel_launch(void* const* d_in, const int* in_sizes, int n_in,
                              void* d_out, int out_size)
{
    const float* hidden = (const float*)d_in[0];
    const float* rotary = (const float*)d_in[1];
    const int*   cu     = (const int*)d_in[2];
    const float* qkv_w  = (const float*)d_in[3];
    const float* qkv_b  = (const float*)d_in[4];
    const float* proj_w = (const float*)d_in[5];
    const float* proj_b = (const float*)d_in[6];
    float* out = (float*)d_out;
    int ncu = in_sizes[2];

    float *qkv_ptr;
    __half *hidH, *wqH, *wpH, *atH;
    cudaGetSymbolAddress((void**)&qkv_ptr, g_qkv);
    cudaGetSymbolAddress((void**)&hidH, g_hid_h);
    cudaGetSymbolAddress((void**)&wqH, g_wq_h);
    cudaGetSymbolAddress((void**)&wpH, g_wp_h);
    cudaGetSymbolAddress((void**)&atH, g_at_h);

    cudaFuncSetAttribute(hgemm1_kernel,
                         cudaFuncAttributeMaxDynamicSharedMemorySize, HG_SMEM);

    // 0) Merged decomposition (hi planes only)
    {
        int total = HID4 + WQ4 + WP4;
        decomp_all_kernel<<<(total + 255) / 256, 256>>>(
            (const float4*)hidden, (const float4*)qkv_w, (const float4*)proj_w,
            (uint32_t*)hidH, (uint32_t*)wqH, (uint32_t*)wpH);
    }

    // 1) QKV GEMM (fp16 1-term)
    hgemm1_kernel<<<dim3(QKV_DIM / 64, SEQ / 128), 256, HG_SMEM>>>(
        hidH, wqH, qkv_b, qkv_ptr, SEQ, QKV_DIM, DIM);

    // 2) Balanced merged prep
    prep_kernel<<<832, 256>>>(rotary);

    // 3) Flash attention
    {
        cudaFuncSetAttribute(fattn_kernel,
                             cudaFuncAttributeMaxDynamicSharedMemorySize, FA_SMEM);
        fattn_kernel<<<dim3(SEQ / AQ, HEADS), 256, FA_SMEM>>>(cu, ncu);
    }

    // 4) proj GEMM (fp16 1-term)
    hgemm1_kernel<<<dim3(DIM / 64, SEQ / 128), 256, HG_SMEM>>>(
        atH, wpH, proj_b, out, SEQ, DIM, DIM);
}